// round 2
// baseline (speedup 1.0000x reference)
#include <cuda_runtime.h>

#define BATCH 2
#define SEQ   2048
#define DIM   1024
#define NH    16
#define HW    64
#define BHTOT (BATCH*NH)
#define MTOT  (BATCH*SEQ)

#define TQ   16
#define TK   128
#define KSTR 68      // 64 + 4 pad: 272B row stride -> conflict-free LDS.128
#define SSTR 2048

// scratch for Q/K/V in (b,h,s,w) layout
__device__ float g_q[BHTOT*SEQ*HW];
__device__ float g_k[BHTOT*SEQ*HW];
__device__ float g_v[BHTOT*SEQ*HW];

// ---------------- fast exp (FMA pipe, avoids MUFU throughput wall) ----------
__device__ __forceinline__ float fexp(float x) {
    x = fmaxf(x, -80.0f);
    const float L = 1.4426950408889634f;   // log2(e)
    float t = fmaf(x, L, 12582912.0f);     // round-to-nearest via magic number
    float n = t - 12582912.0f;
    float r = fmaf(x, L, -n);              // r in [-0.5, 0.5]
    float u = r * 0.6931471805599453f;     // u = r*ln2, |u| <= 0.3466
    // e^u, degree-6 Taylor: rel err ~1e-7
    float p = 1.3888889e-3f;
    p = fmaf(p, u, 8.3333333e-3f);
    p = fmaf(p, u, 4.1666667e-2f);
    p = fmaf(p, u, 1.6666667e-1f);
    p = fmaf(p, u, 5.0e-1f);
    p = fmaf(p, u, 1.0f);
    p = fmaf(p, u, 1.0f);
    int e = (int)n;
    float s = __int_as_float((e + 127) << 23);
    return s * p;
}

// ---------------- QKV projection: y = x @ W^T + b, head-split output --------
// A = x (M=4096, K=1024), B = W (N=1024, K=1024), both K-contiguous.
__global__ __launch_bounds__(256) void qkv_kernel(
    const float* __restrict__ x,
    const float* __restrict__ Wq, const float* __restrict__ bq,
    const float* __restrict__ Wk, const float* __restrict__ bk,
    const float* __restrict__ Wv, const float* __restrict__ bv)
{
    __shared__ float As[8][132];
    __shared__ float Bs[8][132];

    const int z = blockIdx.z;
    const float* Wm = (z == 0) ? Wq : (z == 1) ? Wk : Wv;
    const float* bm = (z == 0) ? bq : (z == 1) ? bk : bv;
    float* outp     = (z == 0) ? g_q : (z == 1) ? g_k : g_v;

    const int t  = threadIdx.x;
    const int m0 = blockIdx.y * 128;
    const int n0 = blockIdx.x * 128;

    const int lrow = t >> 1;          // 0..127
    const int lk4  = (t & 1) * 4;     // 0 or 4

    const int tm = (t & 15) * 8;
    const int tn = (t >> 4) * 8;

    float acc[8][8];
#pragma unroll
    for (int i = 0; i < 8; i++)
#pragma unroll
        for (int j = 0; j < 8; j++) acc[i][j] = 0.0f;

    for (int kt = 0; kt < DIM; kt += 8) {
        float4 va = *(const float4*)&x [(m0 + lrow) * DIM + kt + lk4];
        float4 vb = *(const float4*)&Wm[(n0 + lrow) * DIM + kt + lk4];
        As[lk4 + 0][lrow] = va.x; As[lk4 + 1][lrow] = va.y;
        As[lk4 + 2][lrow] = va.z; As[lk4 + 3][lrow] = va.w;
        Bs[lk4 + 0][lrow] = vb.x; Bs[lk4 + 1][lrow] = vb.y;
        Bs[lk4 + 2][lrow] = vb.z; Bs[lk4 + 3][lrow] = vb.w;
        __syncthreads();

#pragma unroll
        for (int kk = 0; kk < 8; kk++) {
            float4 a0 = *(const float4*)&As[kk][tm];
            float4 a1 = *(const float4*)&As[kk][tm + 4];
            float4 b0 = *(const float4*)&Bs[kk][tn];
            float4 b1 = *(const float4*)&Bs[kk][tn + 4];
            float af[8] = {a0.x, a0.y, a0.z, a0.w, a1.x, a1.y, a1.z, a1.w};
            float bf[8] = {b0.x, b0.y, b0.z, b0.w, b1.x, b1.y, b1.z, b1.w};
#pragma unroll
            for (int i = 0; i < 8; i++)
#pragma unroll
                for (int j = 0; j < 8; j++)
                    acc[i][j] = fmaf(af[i], bf[j], acc[i][j]);
        }
        __syncthreads();
    }

    float bias8[8];
#pragma unroll
    for (int j = 0; j < 8; j++) bias8[j] = bm[n0 + tn + j];

#pragma unroll
    for (int i = 0; i < 8; i++) {
        int m  = m0 + tm + i;
        int bb = m >> 11;            // batch
        int s  = m & (SEQ - 1);      // seq pos
#pragma unroll
        for (int j0 = 0; j0 < 8; j0 += 4) {
            int n = n0 + tn + j0;
            int h = n >> 6;
            int w = n & 63;
            float4 o;
            o.x = acc[i][j0 + 0] + bias8[j0 + 0];
            o.y = acc[i][j0 + 1] + bias8[j0 + 1];
            o.z = acc[i][j0 + 2] + bias8[j0 + 2];
            o.w = acc[i][j0 + 3] + bias8[j0 + 3];
            *(float4*)&outp[(((bb * NH + h) * SEQ) + s) * HW + w] = o;
        }
    }
}

// ---------------- fused attention with double softmax -----------------------
// One block: 16 query rows of one (b,h). Scores tile (16 x 2048) in smem.
__global__ __launch_bounds__(256) void attn_kernel(float* __restrict__ out)
{
    extern __shared__ float sm[];
    float* scores    = sm;                       // TQ * SSTR
    float* ks        = sm + TQ * SSTR;           // TK * KSTR (reused for V)
    float* qs        = ks + TK * KSTR;           // TQ * HW
    float* row_scale = qs + TQ * HW;             // TQ

    const int t  = threadIdx.x;
    const int bh = blockIdx.y;
    const int q0 = blockIdx.x * TQ;

    const float* qg = g_q + (bh * SEQ + q0) * HW;
    const float* kg = g_k + bh * SEQ * HW;
    const float* vg = g_v + bh * SEQ * HW;

    // load Q tile: 16 rows x 16 float4 per row = 256 float4, one per thread
    {
        int qi = t >> 4;           // 0..15
        int d4 = (t & 15) * 4;     // 0..60
        *(float4*)&qs[qi * HW + d4] = *(const float4*)&qg[qi * HW + d4];
    }

    const int qgi = t >> 6;   // 0..3  (4 query rows each)
    const int kl  = t & 63;   // key lane

    // ---- phase 1: scores = Q K^T * scale ----
    for (int kt = 0; kt < SEQ; kt += TK) {
        __syncthreads();
#pragma unroll
        for (int i = 0; i < 8; i++) {
            int f   = t + i * 256;
            int row = f >> 4;
            int c4  = (f & 15) * 4;
            *(float4*)&ks[row * KSTR + c4] =
                *(const float4*)&kg[(kt + row) * HW + c4];
        }
        __syncthreads();

        float acc0[4] = {0, 0, 0, 0};
        float acc1[4] = {0, 0, 0, 0};
#pragma unroll
        for (int d4 = 0; d4 < HW; d4 += 4) {
            float4 k0 = *(const float4*)&ks[kl * KSTR + d4];
            float4 k1 = *(const float4*)&ks[(kl + 64) * KSTR + d4];
#pragma unroll
            for (int a = 0; a < 4; a++) {
                float4 q = *(const float4*)&qs[(qgi * 4 + a) * HW + d4];
                acc0[a] = fmaf(q.x, k0.x, fmaf(q.y, k0.y, fmaf(q.z, k0.z, fmaf(q.w, k0.w, acc0[a]))));
                acc1[a] = fmaf(q.x, k1.x, fmaf(q.y, k1.y, fmaf(q.z, k1.z, fmaf(q.w, k1.w, acc1[a]))));
            }
        }
#pragma unroll
        for (int a = 0; a < 4; a++) {
            scores[(qgi * 4 + a) * SSTR + kt + kl]      = acc0[a] * 0.125f;
            scores[(qgi * 4 + a) * SSTR + kt + kl + 64] = acc1[a] * 0.125f;
        }
    }
    __syncthreads();

    // ---- phase 2: double softmax, per row (2 rows per warp) ----
    const int wid = t >> 5, lane = t & 31;
#pragma unroll
    for (int rr = 0; rr < 2; rr++) {
        int row = wid * 2 + rr;
        float* srow = scores + row * SSTR;

        float m = -1e30f;
        for (int j = lane * 4; j < SEQ; j += 128) {
            float4 s = *(const float4*)&srow[j];
            m = fmaxf(m, fmaxf(fmaxf(s.x, s.y), fmaxf(s.z, s.w)));
        }
#pragma unroll
        for (int o = 16; o > 0; o >>= 1)
            m = fmaxf(m, __shfl_xor_sync(0xffffffffu, m, o));

        float z = 0.0f;
        for (int j = lane * 4; j < SEQ; j += 128) {
            float4 s = *(const float4*)&srow[j];
            s.x = fexp(s.x - m); s.y = fexp(s.y - m);
            s.z = fexp(s.z - m); s.w = fexp(s.w - m);
            *(float4*)&srow[j] = s;
            z += s.x + s.y + s.z + s.w;
        }
#pragma unroll
        for (int o = 16; o > 0; o >>= 1)
            z += __shfl_xor_sync(0xffffffffu, z, o);
        float inv = 1.0f / z;

        // second softmax: inputs p = e*inv in (0,1], no max shift needed
        float z2 = 0.0f;
        for (int j = lane * 4; j < SEQ; j += 128) {
            float4 e = *(const float4*)&srow[j];
            e.x = fexp(e.x * inv); e.y = fexp(e.y * inv);
            e.z = fexp(e.z * inv); e.w = fexp(e.w * inv);
            *(float4*)&srow[j] = e;
            z2 += e.x + e.y + e.z + e.w;
        }
#pragma unroll
        for (int o = 16; o > 0; o >>= 1)
            z2 += __shfl_xor_sync(0xffffffffu, z2, o);
        if (lane == 0) row_scale[row] = 1.0f / z2;  // folded into output
    }

    // ---- phase 3: out = P V (final 1/z2 applied at the write) ----
    float oacc[4] = {0, 0, 0, 0};
    const int wl = t & 63;

    for (int vt = 0; vt < SEQ; vt += TK) {
        __syncthreads();
#pragma unroll
        for (int i = 0; i < 8; i++) {
            int f   = t + i * 256;
            int row = f >> 4;
            int c4  = (f & 15) * 4;
            *(float4*)&ks[row * KSTR + c4] =
                *(const float4*)&vg[(vt + row) * HW + c4];
        }
        __syncthreads();

#pragma unroll 8
        for (int k4 = 0; k4 < TK; k4 += 4) {
            float v0 = ks[(k4 + 0) * KSTR + wl];
            float v1 = ks[(k4 + 1) * KSTR + wl];
            float v2 = ks[(k4 + 2) * KSTR + wl];
            float v3 = ks[(k4 + 3) * KSTR + wl];
#pragma unroll
            for (int a = 0; a < 4; a++) {
                float4 p = *(const float4*)&scores[(qgi * 4 + a) * SSTR + vt + k4];
                oacc[a] = fmaf(p.x, v0, fmaf(p.y, v1, fmaf(p.z, v2, fmaf(p.w, v3, oacc[a]))));
            }
        }
    }

    const int b = bh >> 4, h = bh & 15;
#pragma unroll
    for (int a = 0; a < 4; a++) {
        int qi = qgi * 4 + a;
        out[((b * SEQ + q0 + qi) * DIM) + h * HW + wl] = oacc[a] * row_scale[qi];
    }
}

// ---------------- launch -----------------------------------------------------
extern "C" void kernel_launch(void* const* d_in, const int* in_sizes, int n_in,
                              void* d_out, int out_size)
{
    const float* x  = (const float*)d_in[0];
    const float* Wq = (const float*)d_in[1];
    const float* bq = (const float*)d_in[2];
    const float* Wk = (const float*)d_in[3];
    const float* bk = (const float*)d_in[4];
    const float* Wv = (const float*)d_in[5];
    const float* bv = (const float*)d_in[6];
    float* out = (float*)d_out;

    dim3 g1(DIM / 128, MTOT / 128, 3);
    qkv_kernel<<<g1, 256>>>(x, Wq, bq, Wk, bk, Wv, bv);

    const int smem_bytes = (TQ * SSTR + TK * KSTR + TQ * HW + TQ) * (int)sizeof(float);
    cudaFuncSetAttribute(attn_kernel,
                         cudaFuncAttributeMaxDynamicSharedMemorySize, smem_bytes);
    dim3 g2(SEQ / TQ, BHTOT);
    attn_kernel<<<g2, 256, smem_bytes>>>(out);
}

// round 5
// speedup vs baseline: 3.4355x; 3.4355x over previous
#include <cuda_runtime.h>
#include <cuda_bf16.h>
#include <cstdint>

#define BATCH 2
#define SEQ   2048
#define DIM   1024
#define NH    16
#define HW    64
#define BHTOT (BATCH*NH)
#define MTOT  (BATCH*SEQ)
#define NTOT  (3*DIM)

// ---------------- global scratch ----------------
__device__ __nv_bfloat16 g_xh[MTOT*DIM];
__device__ __nv_bfloat16 g_xl[MTOT*DIM];
__device__ __nv_bfloat16 g_wh[NTOT*DIM];
__device__ __nv_bfloat16 g_wl[NTOT*DIM];
__device__ __nv_bfloat16 g_qb[BHTOT*SEQ*HW];   // (b,h,s,w) bf16
__device__ __nv_bfloat16 g_kb[BHTOT*SEQ*HW];
__device__ __nv_bfloat16 g_vb[BHTOT*SEQ*HW];
__device__ float         g_v [BHTOT*SEQ*HW];   // fp32 V for colsum
__device__ float         g_colsum[BHTOT*HW];

// ---------------- mma.sync / ldmatrix helpers (sm_80+ ISA, works on sm_103) --
__device__ __forceinline__ uint32_t smem_u32(const void* p) {
    uint32_t a;
    asm("{ .reg .u64 t; cvta.to.shared.u64 t, %1; cvt.u32.u64 %0, t; }"
        : "=r"(a) : "l"(p));
    return a;
}
__device__ __forceinline__ void ldsm_x4(uint32_t (&r)[4], uint32_t addr) {
    asm volatile("ldmatrix.sync.aligned.m8n8.x4.shared.b16 {%0,%1,%2,%3}, [%4];"
                 : "=r"(r[0]), "=r"(r[1]), "=r"(r[2]), "=r"(r[3]) : "r"(addr));
}
__device__ __forceinline__ void ldsm_x2(uint32_t (&r)[2], uint32_t addr) {
    asm volatile("ldmatrix.sync.aligned.m8n8.x2.shared.b16 {%0,%1}, [%2];"
                 : "=r"(r[0]), "=r"(r[1]) : "r"(addr));
}
__device__ __forceinline__ void ldsm_x2t(uint32_t (&r)[2], uint32_t addr) {
    asm volatile("ldmatrix.sync.aligned.m8n8.x2.trans.shared.b16 {%0,%1}, [%2];"
                 : "=r"(r[0]), "=r"(r[1]) : "r"(addr));
}
__device__ __forceinline__ void mma_bf16(float (&d)[4], const uint32_t (&a)[4],
                                         const uint32_t (&b)[2]) {
    asm volatile("mma.sync.aligned.m16n8k16.row.col.f32.bf16.bf16.f32 "
                 "{%0,%1,%2,%3}, {%4,%5,%6,%7}, {%8,%9}, {%0,%1,%2,%3};"
                 : "+f"(d[0]), "+f"(d[1]), "+f"(d[2]), "+f"(d[3])
                 : "r"(a[0]), "r"(a[1]), "r"(a[2]), "r"(a[3]),
                   "r"(b[0]), "r"(b[1]));
}

// ---------------- fast exp / expm1 (FMA pipe) -------------------------------
__device__ __forceinline__ float fexp(float x) {
    const float L = 1.4426950408889634f;
    float t = fmaf(x, L, 12582912.0f);
    float n = t - 12582912.0f;
    float r = fmaf(x, L, -n);
    float u = r * 0.6931471805599453f;
    float p = 1.3888889e-3f;
    p = fmaf(p, u, 8.3333333e-3f);
    p = fmaf(p, u, 4.1666667e-2f);
    p = fmaf(p, u, 1.6666667e-1f);
    p = fmaf(p, u, 5.0e-1f);
    p = fmaf(p, u, 1.0f);
    p = fmaf(p, u, 1.0f);
    int e = (int)n;
    return __int_as_float((e + 127) << 23) * p;
}
// expm1 for p in [0, ~1.1]: p * poly(p), deg-8 Taylor, rel err < 3e-6
__device__ __forceinline__ float expm1p(float p) {
    float q = 2.4801587e-5f;
    q = fmaf(q, p, 1.9841270e-4f);
    q = fmaf(q, p, 1.3888889e-3f);
    q = fmaf(q, p, 8.3333333e-3f);
    q = fmaf(q, p, 4.1666667e-2f);
    q = fmaf(q, p, 1.6666667e-1f);
    q = fmaf(q, p, 0.5f);
    q = fmaf(q, p, 1.0f);
    return p * q;
}

// ======================= split kernels ======================================
__global__ __launch_bounds__(256) void split_x_kernel(const float* __restrict__ x)
{
    int i = (blockIdx.x * 256 + threadIdx.x) * 4;
    float4 v = *(const float4*)(x + i);
    __nv_bfloat16 h[4], l[4];
    float f[4] = {v.x, v.y, v.z, v.w};
#pragma unroll
    for (int j = 0; j < 4; j++) {
        h[j] = __float2bfloat16(f[j]);
        l[j] = __float2bfloat16(f[j] - __bfloat162float(h[j]));
    }
    *(uint64_t*)&g_xh[i] = *(const uint64_t*)h;
    *(uint64_t*)&g_xl[i] = *(const uint64_t*)l;
}

__global__ __launch_bounds__(256) void split_w_kernel(
    const float* __restrict__ Wq, const float* __restrict__ Wk,
    const float* __restrict__ Wv)
{
    const int z = blockIdx.y;
    const float* W = (z == 0) ? Wq : (z == 1) ? Wk : Wv;
    int i = (blockIdx.x * 256 + threadIdx.x) * 4;
    float4 v = *(const float4*)(W + i);
    __nv_bfloat16 h[4], l[4];
    float f[4] = {v.x, v.y, v.z, v.w};
#pragma unroll
    for (int j = 0; j < 4; j++) {
        h[j] = __float2bfloat16(f[j]);
        l[j] = __float2bfloat16(f[j] - __bfloat162float(h[j]));
    }
    int o = z * DIM * DIM + i;
    *(uint64_t*)&g_wh[o] = *(const uint64_t*)h;
    *(uint64_t*)&g_wl[o] = *(const uint64_t*)l;
}

// ======================= QKV projection (mma.sync) ==========================
// CTA: 128(M) x 64(N) tile; z selects Q/K/V.  Q,K: 1-term bf16.  V: 3-term.
#define ASTR 40   // 32 + 8 pad (80B rows, conflict-free ldmatrix)

__global__ __launch_bounds__(256) void qkv_kernel(
    const float* __restrict__ bq, const float* __restrict__ bk,
    const float* __restrict__ bv)
{
    __shared__ __align__(16) unsigned short sA[2][128*ASTR];  // hi, lo
    __shared__ __align__(16) unsigned short sB[2][64*ASTR];
    __shared__ float s_bias[64];

    const int t    = threadIdx.x;
    const int wid  = t >> 5;
    const int lane = t & 31;
    const int z    = blockIdx.z;
    const int n0   = blockIdx.x * 64;
    const int m0   = blockIdx.y * 128;
    const bool v3  = (z == 2);

    const __nv_bfloat16* wofs_h = g_wh + (size_t)z * DIM * DIM;
    const __nv_bfloat16* wofs_l = g_wl + (size_t)z * DIM * DIM;

    if (t < 64) {
        const float* bias = (z == 0) ? bq : (z == 1) ? bk : bv;
        s_bias[t] = bias[n0 + t];
    }

    const int wm = wid & 3;      // 4 warps in M (32 rows each)
    const int wn = wid >> 2;     // 2 warps in N (32 cols each)

    const uint32_t sAh_u = smem_u32(sA[0]);
    const uint32_t sAl_u = smem_u32(sA[1]);
    const uint32_t sBh_u = smem_u32(sB[0]);
    const uint32_t sBl_u = smem_u32(sB[1]);

    float d[2][4][4];
#pragma unroll
    for (int i = 0; i < 2; i++)
#pragma unroll
        for (int nf = 0; nf < 4; nf++)
#pragma unroll
            for (int r = 0; r < 4; r++) d[i][nf][r] = 0.0f;

    for (int kc = 0; kc < 32; kc++) {
        const int k0 = kc * 32;
        __syncthreads();
        // A tile: 128 x 32 (hi, + lo if V):  512 uint4
#pragma unroll
        for (int i = 0; i < 2; i++) {
            int idx = t + i * 256;
            int row = idx >> 2, seg = idx & 3;
            const uint4* sh = (const uint4*)&g_xh[(size_t)(m0 + row) * DIM + k0 + seg * 8];
            *(uint4*)((char*)sA[0] + (row * ASTR + seg * 8) * 2) = *sh;
            if (v3) {
                const uint4* sl = (const uint4*)&g_xl[(size_t)(m0 + row) * DIM + k0 + seg * 8];
                *(uint4*)((char*)sA[1] + (row * ASTR + seg * 8) * 2) = *sl;
            }
        }
        // B tile: 64 x 32: 256 uint4
        {
            int row = t >> 2, seg = t & 3;
            const uint4* sh = (const uint4*)&wofs_h[(size_t)(n0 + row) * DIM + k0 + seg * 8];
            *(uint4*)((char*)sB[0] + (row * ASTR + seg * 8) * 2) = *sh;
            if (v3) {
                const uint4* sl = (const uint4*)&wofs_l[(size_t)(n0 + row) * DIM + k0 + seg * 8];
                *(uint4*)((char*)sB[1] + (row * ASTR + seg * 8) * 2) = *sl;
            }
        }
        __syncthreads();

        uint32_t ah[2][2][4], bhf[4][2][2];
        uint32_t al[2][2][4], blf[4][2][2];
#pragma unroll
        for (int i = 0; i < 2; i++)
#pragma unroll
            for (int ks = 0; ks < 2; ks++) {
                uint32_t off = ((wm * 32 + i * 16 + (lane & 15)) * ASTR
                                + ks * 16 + (lane >> 4) * 8) * 2;
                ldsm_x4(ah[i][ks], sAh_u + off);
                if (v3) ldsm_x4(al[i][ks], sAl_u + off);
            }
#pragma unroll
        for (int nf = 0; nf < 4; nf++)
#pragma unroll
            for (int ks = 0; ks < 2; ks++) {
                uint32_t off = ((wn * 32 + nf * 8 + (lane & 7)) * ASTR
                                + ks * 16 + (lane & 8)) * 2;
                ldsm_x2(bhf[nf][ks], sBh_u + off);
                if (v3) ldsm_x2(blf[nf][ks], sBl_u + off);
            }
#pragma unroll
        for (int ks = 0; ks < 2; ks++)
#pragma unroll
            for (int i = 0; i < 2; i++)
#pragma unroll
                for (int nf = 0; nf < 4; nf++) {
                    mma_bf16(d[i][nf], ah[i][ks], bhf[nf][ks]);
                    if (v3) {
                        mma_bf16(d[i][nf], ah[i][ks], blf[nf][ks]);
                        mma_bf16(d[i][nf], al[i][ks], bhf[nf][ks]);
                    }
                }
    }

    // epilogue
    const int h = n0 >> 6;
#pragma unroll
    for (int i = 0; i < 2; i++) {
        int r = m0 + wm * 32 + i * 16 + (lane >> 2);
#pragma unroll
        for (int nf = 0; nf < 4; nf++) {
            int cl = wn * 32 + nf * 8 + 2 * (lane & 3);   // col within head
            float v0 = d[i][nf][0] + s_bias[cl];
            float v1 = d[i][nf][1] + s_bias[cl + 1];
            float v2 = d[i][nf][2] + s_bias[cl];
            float v3v = d[i][nf][3] + s_bias[cl + 1];
#pragma unroll
            for (int half = 0; half < 2; half++) {
                int rr = r + half * 8;
                int b = rr >> 11, s = rr & (SEQ - 1);
                size_t o = ((size_t)((b * NH + h) * SEQ + s)) * HW + cl;
                float e0 = half ? v2 : v0, e1 = half ? v3v : v1;
                __nv_bfloat162 pk = __floats2bfloat162_rn(e0, e1);
                if (z == 0)      *(__nv_bfloat162*)&g_qb[o] = pk;
                else if (z == 1) *(__nv_bfloat162*)&g_kb[o] = pk;
                else {
                    *(__nv_bfloat162*)&g_vb[o] = pk;
                    float2 f2 = {e0, e1};
                    *(float2*)&g_v[o] = f2;
                }
            }
        }
    }
}

// ======================= colsum of V per (b,h) ==============================
__global__ __launch_bounds__(512) void colsum_kernel()
{
    __shared__ float red[512];
    const int bh = blockIdx.x;
    const int t  = threadIdx.x;
    const int w  = t & 63;
    const int sg = t >> 6;            // 8 groups of 256 rows
    const float* vp = g_v + ((size_t)bh * SEQ) * HW;
    float s = 0.0f;
    for (int i = 0; i < 256; i++)
        s += vp[(size_t)(sg * 256 + i) * HW + w];
    red[t] = s;
    __syncthreads();
    if (t < 64) {
        float acc = 0.0f;
#pragma unroll
        for (int g = 0; g < 8; g++) acc += red[g * 64 + t];
        g_colsum[bh * HW + t] = acc;
    }
}

// ======================= fused attention ====================================
// CTA: 32 query rows of one (b,h).  e/u tile 32 x 2048 bf16 in smem.
#define EPAD   2056
#define KVSTR  72
#define OFF_E  0
#define OFF_KV 131584
#define OFF_Q  168448
#define OFF_Z  173056
#define OFF_SC 173184
#define OFF_CS 173312
#define ATTN_SMEM 173568

__global__ __launch_bounds__(256) void attn_kernel(float* __restrict__ out)
{
    extern __shared__ char dsm[];
    char*  e_p   = dsm + OFF_E;
    char*  kv_p  = dsm + OFF_KV;          // 2 buffers of 128*72 bf16
    char*  q_p   = dsm + OFF_Q;
    float* s_z   = (float*)(dsm + OFF_Z);
    float* s_sc  = (float*)(dsm + OFF_SC);
    float* s_cs  = (float*)(dsm + OFF_CS);

    const uint32_t e_u  = smem_u32(e_p);
    const uint32_t kv_u = smem_u32(kv_p);
    const uint32_t q_u  = smem_u32(q_p);

    const int t    = threadIdx.x;
    const int wid  = t >> 5;
    const int lane = t & 31;
    const int q0   = blockIdx.x * 32;
    const int bh   = blockIdx.y;

    const __nv_bfloat16* qg = g_qb + ((size_t)bh * SEQ + q0) * HW;
    const __nv_bfloat16* kg = g_kb + (size_t)bh * SEQ * HW;
    const __nv_bfloat16* vg = g_vb + (size_t)bh * SEQ * HW;

    const int wm = wid & 1;      // 2 warps in M (16 rows)
    const int wn = wid >> 1;     // 4 warps in N
    const int wm16 = wm * 16;

    if (t < 32) s_z[t] = 0.0f;
    if (t < 64) s_cs[t] = g_colsum[bh * HW + t];
    // load Q tile 32x64
    {
        int row = t >> 3, seg = t & 7;
        *(uint4*)(q_p + (row * KVSTR + seg * 8) * 2) =
            *(const uint4*)(qg + row * HW + seg * 8);
    }
    // prologue: K chunk 0 -> buf 0
#pragma unroll
    for (int i = 0; i < 4; i++) {
        int idx = t + i * 256;
        int row = idx >> 3, seg = idx & 7;
        *(uint4*)(kv_p + (row * KVSTR + seg * 8) * 2) =
            *(const uint4*)(kg + row * HW + seg * 8);
    }
    __syncthreads();

    // preload Q a-frags (persist across chunks)
    uint32_t aq[4][4];
#pragma unroll
    for (int ks = 0; ks < 4; ks++) {
        uint32_t off = ((wm16 + (lane & 15)) * KVSTR + ks * 16 + (lane >> 4) * 8) * 2;
        ldsm_x4(aq[ks], q_u + off);
    }

    float zp0 = 0.0f, zp1 = 0.0f;
    const int erow = wm16 + (lane >> 2);

    // ---- phase 1: e = exp(QK^T/8), partial z ----
    for (int c = 0; c < 16; c++) {
        if (c < 15) {
            const __nv_bfloat16* src = kg + (size_t)(c + 1) * 128 * HW;
            char* dst = kv_p + ((c + 1) & 1) * (128 * KVSTR * 2);
#pragma unroll
            for (int i = 0; i < 4; i++) {
                int idx = t + i * 256;
                int row = idx >> 3, seg = idx & 7;
                *(uint4*)(dst + (row * KVSTR + seg * 8) * 2) =
                    *(const uint4*)(src + row * HW + seg * 8);
            }
        }
        const uint32_t buf = kv_u + (c & 1) * (128 * KVSTR * 2);

        float d[4][4];
#pragma unroll
        for (int nf = 0; nf < 4; nf++)
#pragma unroll
            for (int r = 0; r < 4; r++) d[nf][r] = 0.0f;

#pragma unroll
        for (int ks = 0; ks < 4; ks++) {
#pragma unroll
            for (int nf = 0; nf < 4; nf++) {
                uint32_t b[2];
                uint32_t off = ((wn * 32 + nf * 8 + (lane & 7)) * KVSTR
                                + ks * 16 + (lane & 8)) * 2;
                ldsm_x2(b, buf + off);
                mma_bf16(d[nf], aq[ks], b);
            }
        }
#pragma unroll
        for (int nf = 0; nf < 4; nf++) {
            float e0 = fexp(d[nf][0] * 0.125f);
            float e1 = fexp(d[nf][1] * 0.125f);
            float e2 = fexp(d[nf][2] * 0.125f);
            float e3 = fexp(d[nf][3] * 0.125f);
            zp0 += e0 + e1;
            zp1 += e2 + e3;
            int col = c * 128 + wn * 32 + nf * 8 + 2 * (lane & 3);
            *(__nv_bfloat162*)(e_p + (erow * EPAD + col) * 2) =
                __floats2bfloat162_rn(e0, e1);
            *(__nv_bfloat162*)(e_p + ((erow + 8) * EPAD + col) * 2) =
                __floats2bfloat162_rn(e2, e3);
        }
        __syncthreads();
    }

    // z reduce (lanes sharing a row: xor 1, 2)
    zp0 += __shfl_xor_sync(0xffffffffu, zp0, 1);
    zp0 += __shfl_xor_sync(0xffffffffu, zp0, 2);
    zp1 += __shfl_xor_sync(0xffffffffu, zp1, 1);
    zp1 += __shfl_xor_sync(0xffffffffu, zp1, 2);
    if ((lane & 3) == 0) {
        atomicAdd(&s_z[erow], zp0);
        atomicAdd(&s_z[erow + 8], zp1);
    }
    __syncthreads();

    // ---- phase 2: u = expm1(e/z), in place, per-row scale ----
    {
        int r0 = wid * 4;
#pragma unroll
        for (int rr = 0; rr < 4; rr++) {
            int r = r0 + rr;
            float inv = 1.0f / s_z[r];
            float zu = 0.0f;
            uint32_t* rowp = (uint32_t*)(e_p + r * EPAD * 2);
#pragma unroll 4
            for (int it = 0; it < 32; it++) {
                int jj = it * 32 + lane;
                uint32_t bits = rowp[jj];
                float e0 = __uint_as_float(bits << 16);
                float e1 = __uint_as_float(bits & 0xffff0000u);
                float u0 = expm1p(e0 * inv);
                float u1 = expm1p(e1 * inv);
                zu += u0 + u1;
                *(__nv_bfloat162*)&rowp[jj] = __floats2bfloat162_rn(u0, u1);
            }
#pragma unroll
            for (int o = 16; o > 0; o >>= 1)
                zu += __shfl_xor_sync(0xffffffffu, zu, o);
            if (lane == 0) s_sc[r] = 1.0f / (2048.0f + zu);
        }
    }
    __syncthreads();

    // ---- phase 3: D = u @ V ----
    // prologue: V chunk 0 -> buf 0
#pragma unroll
    for (int i = 0; i < 4; i++) {
        int idx = t + i * 256;
        int row = idx >> 3, seg = idx & 7;
        *(uint4*)(kv_p + (row * KVSTR + seg * 8) * 2) =
            *(const uint4*)(vg + row * HW + seg * 8);
    }
    __syncthreads();

    float dd[2][4];
#pragma unroll
    for (int nf = 0; nf < 2; nf++)
#pragma unroll
        for (int r = 0; r < 4; r++) dd[nf][r] = 0.0f;

    for (int c = 0; c < 16; c++) {
        if (c < 15) {
            const __nv_bfloat16* src = vg + (size_t)(c + 1) * 128 * HW;
            char* dst = kv_p + ((c + 1) & 1) * (128 * KVSTR * 2);
#pragma unroll
            for (int i = 0; i < 4; i++) {
                int idx = t + i * 256;
                int row = idx >> 3, seg = idx & 7;
                *(uint4*)(dst + (row * KVSTR + seg * 8) * 2) =
                    *(const uint4*)(src + row * HW + seg * 8);
            }
        }
        const uint32_t buf = kv_u + (c & 1) * (128 * KVSTR * 2);

#pragma unroll
        for (int ks = 0; ks < 8; ks++) {
            uint32_t au[4];
            uint32_t aoff = ((wm16 + (lane & 15)) * EPAD
                             + c * 128 + ks * 16 + (lane >> 4) * 8) * 2;
            ldsm_x4(au, e_u + aoff);
#pragma unroll
            for (int nf = 0; nf < 2; nf++) {
                uint32_t b[2];
                uint32_t boff = ((ks * 16 + (lane & 7) + (lane & 8)) * KVSTR
                                 + wn * 16 + nf * 8) * 2;
                ldsm_x2t(b, buf + boff);
                mma_bf16(dd[nf], au, b);
            }
        }
        __syncthreads();
    }

    // ---- epilogue: h = (colsum + D) * scale ----
    {
        const int b  = bh >> 4, hh = bh & 15;
        const int r  = wm16 + (lane >> 2);
        float sc0 = s_sc[r], sc8 = s_sc[r + 8];
#pragma unroll
        for (int nf = 0; nf < 2; nf++) {
            int w = wn * 16 + nf * 8 + 2 * (lane & 3);
            float cs0 = s_cs[w], cs1 = s_cs[w + 1];
            float2 o0 = { (cs0 + dd[nf][0]) * sc0, (cs1 + dd[nf][1]) * sc0 };
            float2 o1 = { (cs0 + dd[nf][2]) * sc8, (cs1 + dd[nf][3]) * sc8 };
            *(float2*)&out[((size_t)(b * SEQ + q0 + r)) * DIM + hh * HW + w] = o0;
            *(float2*)&out[((size_t)(b * SEQ + q0 + r + 8)) * DIM + hh * HW + w] = o1;
        }
    }
}

// ---------------- launch -----------------------------------------------------
extern "C" void kernel_launch(void* const* d_in, const int* in_sizes, int n_in,
                              void* d_out, int out_size)
{
    const float* x  = (const float*)d_in[0];
    const float* bq = (const float*)d_in[2];
    const float* bk = (const float*)d_in[4];
    const float* bv = (const float*)d_in[6];
    const float* Wq = (const float*)d_in[1];
    const float* Wk = (const float*)d_in[3];
    const float* Wv = (const float*)d_in[5];
    float* out = (float*)d_out;

    split_x_kernel<<<MTOT * DIM / 1024, 256>>>(x);
    {
        dim3 gw(DIM * DIM / 1024, 3);
        split_w_kernel<<<gw, 256>>>(Wq, Wk, Wv);
    }
    {
        dim3 g(DIM / 64, MTOT / 128, 3);
        qkv_kernel<<<g, 256>>>(bq, bk, bv);
    }
    colsum_kernel<<<BHTOT, 512>>>();
    {
        cudaFuncSetAttribute(attn_kernel,
                             cudaFuncAttributeMaxDynamicSharedMemorySize, ATTN_SMEM);
        dim3 g2(SEQ / 32, BHTOT);
        attn_kernel<<<g2, 256, ATTN_SMEM>>>(out);
    }
}

// round 7
// speedup vs baseline: 4.0510x; 1.1791x over previous
#include <cuda_runtime.h>
#include <cuda_bf16.h>
#include <cstdint>

#define BATCH 2
#define SEQ   2048
#define DIM   1024
#define NH    16
#define HW    64
#define BHTOT (BATCH*NH)
#define MTOT  (BATCH*SEQ)

// ---------------- global scratch ----------------
__device__ __nv_bfloat16 g_xh[MTOT*DIM];
__device__ __nv_bfloat16 g_wh[3*DIM*DIM];
__device__ __nv_bfloat16 g_qb[BHTOT*SEQ*HW];   // (b,h,s,w) bf16
__device__ __nv_bfloat16 g_kb[BHTOT*SEQ*HW];
__device__ __nv_bfloat16 g_vb[BHTOT*SEQ*HW];
__device__ float         g_sx[BATCH*DIM];      // sum_s x[b,s,:]
__device__ float         g_colsum[BHTOT*HW];

// ---------------- mma.sync / ldmatrix helpers -------------------------------
__device__ __forceinline__ uint32_t smem_u32(const void* p) {
    uint32_t a;
    asm("{ .reg .u64 t; cvta.to.shared.u64 t, %1; cvt.u32.u64 %0, t; }"
        : "=r"(a) : "l"(p));
    return a;
}
__device__ __forceinline__ void ldsm_x4(uint32_t (&r)[4], uint32_t addr) {
    asm volatile("ldmatrix.sync.aligned.m8n8.x4.shared.b16 {%0,%1,%2,%3}, [%4];"
                 : "=r"(r[0]), "=r"(r[1]), "=r"(r[2]), "=r"(r[3]) : "r"(addr));
}
__device__ __forceinline__ void ldsm_x2(uint32_t (&r)[2], uint32_t addr) {
    asm volatile("ldmatrix.sync.aligned.m8n8.x2.shared.b16 {%0,%1}, [%2];"
                 : "=r"(r[0]), "=r"(r[1]) : "r"(addr));
}
__device__ __forceinline__ void ldsm_x2t(uint32_t (&r)[2], uint32_t addr) {
    asm volatile("ldmatrix.sync.aligned.m8n8.x2.trans.shared.b16 {%0,%1}, [%2];"
                 : "=r"(r[0]), "=r"(r[1]) : "r"(addr));
}
__device__ __forceinline__ void mma_bf16(float (&d)[4], const uint32_t (&a)[4],
                                         const uint32_t (&b)[2]) {
    asm volatile("mma.sync.aligned.m16n8k16.row.col.f32.bf16.bf16.f32 "
                 "{%0,%1,%2,%3}, {%4,%5,%6,%7}, {%8,%9}, {%0,%1,%2,%3};"
                 : "+f"(d[0]), "+f"(d[1]), "+f"(d[2]), "+f"(d[3])
                 : "r"(a[0]), "r"(a[1]), "r"(a[2]), "r"(a[3]),
                   "r"(b[0]), "r"(b[1]));
}

// ---------------- fast exp / expm1 (FMA pipe) -------------------------------
__device__ __forceinline__ float fexp(float x) {
    const float L = 1.4426950408889634f;
    float t = fmaf(x, L, 12582912.0f);
    float n = t - 12582912.0f;
    float r = fmaf(x, L, -n);
    float u = r * 0.6931471805599453f;
    float p = 1.3888889e-3f;
    p = fmaf(p, u, 8.3333333e-3f);
    p = fmaf(p, u, 4.1666667e-2f);
    p = fmaf(p, u, 1.6666667e-1f);
    p = fmaf(p, u, 5.0e-1f);
    p = fmaf(p, u, 1.0f);
    p = fmaf(p, u, 1.0f);
    int e = (int)n;
    return __int_as_float((e + 127) << 23) * p;
}
__device__ __forceinline__ float expm1p(float p) {
    float q = 2.4801587e-5f;
    q = fmaf(q, p, 1.9841270e-4f);
    q = fmaf(q, p, 1.3888889e-3f);
    q = fmaf(q, p, 8.3333333e-3f);
    q = fmaf(q, p, 4.1666667e-2f);
    q = fmaf(q, p, 1.6666667e-1f);
    q = fmaf(q, p, 0.5f);
    q = fmaf(q, p, 1.0f);
    return p * q;
}

// ======================= bf16 casts (hi only) ===============================
__global__ __launch_bounds__(256) void split_x_kernel(const float* __restrict__ x)
{
    int i = (blockIdx.x * 256 + threadIdx.x) * 4;
    float4 v = *(const float4*)(x + i);
    __nv_bfloat16 h[4] = {
        __float2bfloat16(v.x), __float2bfloat16(v.y),
        __float2bfloat16(v.z), __float2bfloat16(v.w) };
    *(uint64_t*)&g_xh[i] = *(const uint64_t*)h;
}

__global__ __launch_bounds__(256) void split_w_kernel(
    const float* __restrict__ Wq, const float* __restrict__ Wk,
    const float* __restrict__ Wv)
{
    const int z = blockIdx.y;
    const float* W = (z == 0) ? Wq : (z == 1) ? Wk : Wv;
    int i = (blockIdx.x * 256 + threadIdx.x) * 4;
    float4 v = *(const float4*)(W + i);
    __nv_bfloat16 h[4] = {
        __float2bfloat16(v.x), __float2bfloat16(v.y),
        __float2bfloat16(v.z), __float2bfloat16(v.w) };
    *(uint64_t*)&g_wh[(size_t)z * DIM * DIM + i] = *(const uint64_t*)h;
}

// ======================= exact colsum via rank-1 identity ===================
__global__ __launch_bounds__(256) void sumx_kernel(const float* __restrict__ x)
{
    const int d = blockIdx.x * 256 + threadIdx.x;
    const int b = blockIdx.y;
    const float* xp = x + (size_t)b * SEQ * DIM + d;
    float s0 = 0, s1 = 0, s2 = 0, s3 = 0;
    for (int s = 0; s < SEQ; s += 4) {
        s0 += xp[(size_t)(s + 0) * DIM];
        s1 += xp[(size_t)(s + 1) * DIM];
        s2 += xp[(size_t)(s + 2) * DIM];
        s3 += xp[(size_t)(s + 3) * DIM];
    }
    g_sx[b * DIM + d] = (s0 + s1) + (s2 + s3);
}

// colsumV[b, n] = g_sx[b,:] . Wv[n,:] + 2048*bv[n];  one warp per (b,n)
__global__ __launch_bounds__(256) void colsumv_kernel(
    const float* __restrict__ Wv, const float* __restrict__ bv)
{
    const int wid  = threadIdx.x >> 5;
    const int lane = threadIdx.x & 31;
    const int gw   = blockIdx.x * 8 + wid;       // 0..2047
    const int n    = gw & (DIM - 1);
    const int b    = gw >> 10;
    const float* wr = Wv + (size_t)n * DIM;
    const float* sx = g_sx + b * DIM;
    float acc = 0.0f;
#pragma unroll
    for (int it = 0; it < 8; it++) {
        int j = (it * 32 + lane) * 4;
        float4 w4 = *(const float4*)(wr + j);
        float4 s4 = *(const float4*)(sx + j);
        acc += w4.x * s4.x + w4.y * s4.y + w4.z * s4.z + w4.w * s4.w;
    }
#pragma unroll
    for (int o = 16; o > 0; o >>= 1)
        acc += __shfl_xor_sync(0xffffffffu, acc, o);
    if (lane == 0) {
        int h = n >> 6, w = n & 63;
        g_colsum[(b * NH + h) * HW + w] = acc + 2048.0f * bv[n];
    }
}

// ======================= QKV projection (mma.sync, 1-term bf16) =============
#define ASTR 40   // 32 + 8 pad

__global__ __launch_bounds__(256) void qkv_kernel(
    const float* __restrict__ bq, const float* __restrict__ bk,
    const float* __restrict__ bv)
{
    __shared__ __align__(16) unsigned short sA[128*ASTR];
    __shared__ __align__(16) unsigned short sB[64*ASTR];
    __shared__ float s_bias[64];

    const int t    = threadIdx.x;
    const int wid  = t >> 5;
    const int lane = t & 31;
    const int z    = blockIdx.z;
    const int n0   = blockIdx.x * 64;
    const int m0   = blockIdx.y * 128;

    const __nv_bfloat16* wofs = g_wh + (size_t)z * DIM * DIM;

    if (t < 64) {
        const float* bias = (z == 0) ? bq : (z == 1) ? bk : bv;
        s_bias[t] = bias[n0 + t];
    }

    const int wm = wid & 3;
    const int wn = wid >> 2;
    const uint32_t sA_u = smem_u32(sA);
    const uint32_t sB_u = smem_u32(sB);

    float d[2][4][4];
#pragma unroll
    for (int i = 0; i < 2; i++)
#pragma unroll
        for (int nf = 0; nf < 4; nf++)
#pragma unroll
            for (int r = 0; r < 4; r++) d[i][nf][r] = 0.0f;

    for (int kc = 0; kc < 32; kc++) {
        const int k0 = kc * 32;
        __syncthreads();
#pragma unroll
        for (int i = 0; i < 2; i++) {
            int idx = t + i * 256;
            int row = idx >> 2, seg = idx & 3;
            *(uint4*)((char*)sA + (row * ASTR + seg * 8) * 2) =
                *(const uint4*)&g_xh[(size_t)(m0 + row) * DIM + k0 + seg * 8];
        }
        {
            int row = t >> 2, seg = t & 3;
            *(uint4*)((char*)sB + (row * ASTR + seg * 8) * 2) =
                *(const uint4*)&wofs[(size_t)(n0 + row) * DIM + k0 + seg * 8];
        }
        __syncthreads();

        uint32_t ah[2][2][4], bf[4][2][2];
#pragma unroll
        for (int i = 0; i < 2; i++)
#pragma unroll
            for (int ks = 0; ks < 2; ks++) {
                uint32_t off = ((wm * 32 + i * 16 + (lane & 15)) * ASTR
                                + ks * 16 + (lane >> 4) * 8) * 2;
                ldsm_x4(ah[i][ks], sA_u + off);
            }
#pragma unroll
        for (int nf = 0; nf < 4; nf++)
#pragma unroll
            for (int ks = 0; ks < 2; ks++) {
                uint32_t off = ((wn * 32 + nf * 8 + (lane & 7)) * ASTR
                                + ks * 16 + (lane & 8)) * 2;
                ldsm_x2(bf[nf][ks], sB_u + off);
            }
#pragma unroll
        for (int ks = 0; ks < 2; ks++)
#pragma unroll
            for (int i = 0; i < 2; i++)
#pragma unroll
                for (int nf = 0; nf < 4; nf++)
                    mma_bf16(d[i][nf], ah[i][ks], bf[nf][ks]);
    }

    const int h = n0 >> 6;
    __nv_bfloat16* outp = (z == 0) ? g_qb : (z == 1) ? g_kb : g_vb;
#pragma unroll
    for (int i = 0; i < 2; i++) {
        int r = m0 + wm * 32 + i * 16 + (lane >> 2);
#pragma unroll
        for (int nf = 0; nf < 4; nf++) {
            int cl = wn * 32 + nf * 8 + 2 * (lane & 3);
            float v0 = d[i][nf][0] + s_bias[cl];
            float v1 = d[i][nf][1] + s_bias[cl + 1];
            float v2 = d[i][nf][2] + s_bias[cl];
            float v3 = d[i][nf][3] + s_bias[cl + 1];
#pragma unroll
            for (int half = 0; half < 2; half++) {
                int rr = r + half * 8;
                int b = rr >> 11, s = rr & (SEQ - 1);
                size_t o = ((size_t)((b * NH + h) * SEQ + s)) * HW + cl;
                *(__nv_bfloat162*)&outp[o] =
                    __floats2bfloat162_rn(half ? v2 : v0, half ? v3 : v1);
            }
        }
    }
}

// ======================= fused attention (512 threads) ======================
#define EPAD   2056
#define KVSTR  72
#define OFF_E    0
#define OFF_KV   131584
#define OFF_Q    168448
#define OFF_OUT  173056
#define OFF_Z    181248
#define OFF_SC   181376
#define OFF_CS   181504
#define ATTN_SMEM 181760

__global__ __launch_bounds__(512) void attn_kernel(float* __restrict__ out)
{
    extern __shared__ char dsm[];
    char*  e_p   = dsm + OFF_E;
    char*  kv_p  = dsm + OFF_KV;
    char*  q_p   = dsm + OFF_Q;
    float* s_out = (float*)(dsm + OFF_OUT);       // 32 x 64 fp32
    float* s_z   = (float*)(dsm + OFF_Z);
    float* s_sc  = (float*)(dsm + OFF_SC);
    float* s_cs  = (float*)(dsm + OFF_CS);

    const uint32_t e_u  = smem_u32(e_p);
    const uint32_t kv_u = smem_u32(kv_p);
    const uint32_t q_u  = smem_u32(q_p);

    const int t    = threadIdx.x;
    const int wid  = t >> 5;
    const int lane = t & 31;
    const int q0   = blockIdx.x * 32;
    const int bh   = blockIdx.y;

    const __nv_bfloat16* qg = g_qb + ((size_t)bh * SEQ + q0) * HW;
    const __nv_bfloat16* kg = g_kb + (size_t)bh * SEQ * HW;
    const __nv_bfloat16* vg = g_vb + (size_t)bh * SEQ * HW;

    const int wm   = wid & 1;       // 16-row half
    const int wm16 = wm * 16;

    if (t < 32) s_z[t] = 0.0f;
    if (t < 64) s_cs[t] = g_colsum[bh * HW + t];
    if (t < 256) {                  // Q tile 32x64
        int row = t >> 3, seg = t & 7;
        *(uint4*)(q_p + (row * KVSTR + seg * 8) * 2) =
            *(const uint4*)(qg + row * HW + seg * 8);
    }
    // K chunk 0 -> buf 0 (1024 uint4, 2 per thread)
#pragma unroll
    for (int i = 0; i < 2; i++) {
        int idx = t + i * 512;
        int row = idx >> 3, seg = idx & 7;
        *(uint4*)(kv_p + (row * KVSTR + seg * 8) * 2) =
            *(const uint4*)(kg + row * HW + seg * 8);
    }
    __syncthreads();

    uint32_t aq[4][4];
#pragma unroll
    for (int ks = 0; ks < 4; ks++) {
        uint32_t off = ((wm16 + (lane & 15)) * KVSTR + ks * 16 + (lane >> 4) * 8) * 2;
        ldsm_x4(aq[ks], q_u + off);
    }

    float zp0 = 0.0f, zp1 = 0.0f;
    const int erow = wm16 + (lane >> 2);
    const int wq   = wid >> 1;      // 0..7: 16-col group within a 128-chunk

    // ---- phase 1: e = exp(QK^T/8) ----
    for (int c = 0; c < 16; c++) {
        if (c < 15) {
            const __nv_bfloat16* src = kg + (size_t)(c + 1) * 128 * HW;
            char* dst = kv_p + ((c + 1) & 1) * (128 * KVSTR * 2);
#pragma unroll
            for (int i = 0; i < 2; i++) {
                int idx = t + i * 512;
                int row = idx >> 3, seg = idx & 7;
                *(uint4*)(dst + (row * KVSTR + seg * 8) * 2) =
                    *(const uint4*)(src + row * HW + seg * 8);
            }
        }
        const uint32_t buf = kv_u + (c & 1) * (128 * KVSTR * 2);

#pragma unroll
        for (int nf = 0; nf < 2; nf++) {
            float d[4] = {0, 0, 0, 0};
#pragma unroll
            for (int ks = 0; ks < 4; ks++) {
                uint32_t b[2];
                uint32_t off = ((wq * 16 + nf * 8 + (lane & 7)) * KVSTR
                                + ks * 16 + (lane & 8)) * 2;
                ldsm_x2(b, buf + off);
                mma_bf16(d, aq[ks], b);
            }
            float e0 = fexp(d[0] * 0.125f);
            float e1 = fexp(d[1] * 0.125f);
            float e2 = fexp(d[2] * 0.125f);
            float e3 = fexp(d[3] * 0.125f);
            zp0 += e0 + e1;
            zp1 += e2 + e3;
            int col = c * 128 + wq * 16 + nf * 8 + 2 * (lane & 3);
            *(__nv_bfloat162*)(e_p + (erow * EPAD + col) * 2) =
                __floats2bfloat162_rn(e0, e1);
            *(__nv_bfloat162*)(e_p + ((erow + 8) * EPAD + col) * 2) =
                __floats2bfloat162_rn(e2, e3);
        }
        __syncthreads();
    }

    zp0 += __shfl_xor_sync(0xffffffffu, zp0, 1);
    zp0 += __shfl_xor_sync(0xffffffffu, zp0, 2);
    zp1 += __shfl_xor_sync(0xffffffffu, zp1, 1);
    zp1 += __shfl_xor_sync(0xffffffffu, zp1, 2);
    if ((lane & 3) == 0) {
        atomicAdd(&s_z[erow], zp0);
        atomicAdd(&s_z[erow + 8], zp1);
    }
    __syncthreads();

    // ---- phase 2: u = expm1(e/z), 2 rows per warp ----
    {
#pragma unroll
        for (int rr = 0; rr < 2; rr++) {
            int r = wid * 2 + rr;
            float inv = 1.0f / s_z[r];
            float zu = 0.0f;
            uint32_t* rowp = (uint32_t*)(e_p + r * EPAD * 2);
#pragma unroll 4
            for (int it = 0; it < 32; it++) {
                int jj = it * 32 + lane;
                uint32_t bits = rowp[jj];
                float e0 = __uint_as_float(bits << 16);
                float e1 = __uint_as_float(bits & 0xffff0000u);
                float u0 = expm1p(e0 * inv);
                float u1 = expm1p(e1 * inv);
                zu += u0 + u1;
                *(__nv_bfloat162*)&rowp[jj] = __floats2bfloat162_rn(u0, u1);
            }
#pragma unroll
            for (int o = 16; o > 0; o >>= 1)
                zu += __shfl_xor_sync(0xffffffffu, zu, o);
            if (lane == 0) s_sc[r] = 1.0f / (2048.0f + zu);
        }
    }

    // zero output accumulation tile
    *(float4*)&s_out[t * 4] = make_float4(0.f, 0.f, 0.f, 0.f);
    __syncthreads();

    // ---- phase 3: D = u @ V  (wm2 x wn2 x wk2 warp layout) ----
#pragma unroll
    for (int i = 0; i < 2; i++) {
        int idx = t + i * 512;
        int row = idx >> 3, seg = idx & 7;
        *(uint4*)(kv_p + (row * KVSTR + seg * 8) * 2) =
            *(const uint4*)(vg + row * HW + seg * 8);
    }
    __syncthreads();

    const int wn = (wid >> 1) & 1;   // 32-col half
    const int wk = wid >> 2;         // 0..3: 32-wide K slice within chunk

    float dd[4][4];
#pragma unroll
    for (int nf = 0; nf < 4; nf++)
#pragma unroll
        for (int r = 0; r < 4; r++) dd[nf][r] = 0.0f;

    for (int c = 0; c < 16; c++) {
        if (c < 15) {
            const __nv_bfloat16* src = vg + (size_t)(c + 1) * 128 * HW;
            char* dst = kv_p + ((c + 1) & 1) * (128 * KVSTR * 2);
#pragma unroll
            for (int i = 0; i < 2; i++) {
                int idx = t + i * 512;
                int row = idx >> 3, seg = idx & 7;
                *(uint4*)(dst + (row * KVSTR + seg * 8) * 2) =
                    *(const uint4*)(src + row * HW + seg * 8);
            }
        }
        const uint32_t buf = kv_u + (c & 1) * (128 * KVSTR * 2);

#pragma unroll
        for (int ks = 0; ks < 2; ks++) {
            uint32_t au[4];
            uint32_t aoff = ((wm16 + (lane & 15)) * EPAD
                             + c * 128 + wk * 32 + ks * 16 + (lane >> 4) * 8) * 2;
            ldsm_x4(au, e_u + aoff);
#pragma unroll
            for (int nf = 0; nf < 4; nf++) {
                uint32_t b[2];
                uint32_t boff = ((wk * 32 + ks * 16 + (lane & 7) + (lane & 8)) * KVSTR
                                 + wn * 32 + nf * 8) * 2;
                ldsm_x2t(b, buf + boff);
                mma_bf16(dd[nf], au, b);
            }
        }
        __syncthreads();
    }

    // reduce wk partials into s_out
    {
        int row0 = wm16 + (lane >> 2);
#pragma unroll
        for (int nf = 0; nf < 4; nf++) {
            int col = wn * 32 + nf * 8 + 2 * (lane & 3);
            atomicAdd(&s_out[row0 * 64 + col],       dd[nf][0]);
            atomicAdd(&s_out[row0 * 64 + col + 1],   dd[nf][1]);
            atomicAdd(&s_out[(row0 + 8) * 64 + col],     dd[nf][2]);
            atomicAdd(&s_out[(row0 + 8) * 64 + col + 1], dd[nf][3]);
        }
    }
    __syncthreads();

    // ---- epilogue: h = (colsum + D) * scale ----
    {
        const int b  = bh >> 4, hh = bh & 15;
        const int row = t >> 4;
        const int c0  = (t & 15) * 4;
        float sc = s_sc[row];
        float4 a = *(float4*)&s_out[row * 64 + c0];
        float4 cs = *(float4*)&s_cs[c0];
        float4 o = { (cs.x + a.x) * sc, (cs.y + a.y) * sc,
                     (cs.z + a.z) * sc, (cs.w + a.w) * sc };
        *(float4*)&out[((size_t)(b * SEQ + q0 + row)) * DIM + hh * HW + c0] = o;
    }
}

// ---------------- launch -----------------------------------------------------
extern "C" void kernel_launch(void* const* d_in, const int* in_sizes, int n_in,
                              void* d_out, int out_size)
{
    const float* x  = (const float*)d_in[0];
    const float* Wq = (const float*)d_in[1];
    const float* bq = (const float*)d_in[2];
    const float* Wk = (const float*)d_in[3];
    const float* bk = (const float*)d_in[4];
    const float* Wv = (const float*)d_in[5];
    const float* bv = (const float*)d_in[6];
    float* out = (float*)d_out;

    split_x_kernel<<<MTOT * DIM / 1024, 256>>>(x);
    {
        dim3 gw(DIM * DIM / 1024, 3);
        split_w_kernel<<<gw, 256>>>(Wq, Wk, Wv);
    }
    {
        dim3 gs(DIM / 256, BATCH);
        sumx_kernel<<<gs, 256>>>(x);
    }
    colsumv_kernel<<<BATCH * DIM / 8, 256>>>(Wv, bv);
    {
        dim3 g(DIM / 64, MTOT / 128, 3);
        qkv_kernel<<<g, 256>>>(bq, bk, bv);
    }
    {
        cudaFuncSetAttribute(attn_kernel,
                             cudaFuncAttributeMaxDynamicSharedMemorySize, ATTN_SMEM);
        dim3 g2(SEQ / 32, BHTOT);
        attn_kernel<<<g2, 512, ATTN_SMEM>>>(out);
    }
}

// round 11
// speedup vs baseline: 4.6911x; 1.1580x over previous
#include <cuda_runtime.h>
#include <cuda_bf16.h>
#include <cstdint>

#define BATCH 2
#define SEQ   2048
#define DIM   1024
#define NH    16
#define HW    64
#define BHTOT (BATCH*NH)
#define MTOT  (BATCH*SEQ)

// ---------------- global scratch ----------------
__device__ __nv_bfloat16 g_xh[MTOT*DIM];
__device__ __nv_bfloat16 g_wh[3*DIM*DIM];
__device__ __nv_bfloat16 g_qb[BHTOT*SEQ*HW];
__device__ __nv_bfloat16 g_kb[BHTOT*SEQ*HW];
__device__ __nv_bfloat16 g_vb[BHTOT*SEQ*HW];
__device__ float         g_sx[BATCH*DIM];
__device__ float         g_colsum[BHTOT*HW];

// ---------------- helpers ---------------------------------------------------
__device__ __forceinline__ uint32_t smem_u32(const void* p) {
    uint32_t a;
    asm("{ .reg .u64 t; cvta.to.shared.u64 t, %1; cvt.u32.u64 %0, t; }"
        : "=r"(a) : "l"(p));
    return a;
}
__device__ __forceinline__ void ldsm_x4(uint32_t (&r)[4], uint32_t addr) {
    asm volatile("ldmatrix.sync.aligned.m8n8.x4.shared.b16 {%0,%1,%2,%3}, [%4];"
                 : "=r"(r[0]), "=r"(r[1]), "=r"(r[2]), "=r"(r[3]) : "r"(addr));
}
__device__ __forceinline__ void ldsm_x2(uint32_t (&r)[2], uint32_t addr) {
    asm volatile("ldmatrix.sync.aligned.m8n8.x2.shared.b16 {%0,%1}, [%2];"
                 : "=r"(r[0]), "=r"(r[1]) : "r"(addr));
}
__device__ __forceinline__ void ldsm_x2t(uint32_t (&r)[2], uint32_t addr) {
    asm volatile("ldmatrix.sync.aligned.m8n8.x2.trans.shared.b16 {%0,%1}, [%2];"
                 : "=r"(r[0]), "=r"(r[1]) : "r"(addr));
}
__device__ __forceinline__ void mma_bf16(float (&d)[4], const uint32_t (&a)[4],
                                         const uint32_t (&b)[2]) {
    asm volatile("mma.sync.aligned.m16n8k16.row.col.f32.bf16.bf16.f32 "
                 "{%0,%1,%2,%3}, {%4,%5,%6,%7}, {%8,%9}, {%0,%1,%2,%3};"
                 : "+f"(d[0]), "+f"(d[1]), "+f"(d[2]), "+f"(d[3])
                 : "r"(a[0]), "r"(a[1]), "r"(a[2]), "r"(a[3]),
                   "r"(b[0]), "r"(b[1]));
}
#define CP16(dst, src) \
    asm volatile("cp.async.cg.shared.global [%0], [%1], 16;" \
                 :: "r"(dst), "l"(src))
#define CP_COMMIT() asm volatile("cp.async.commit_group;" ::: "memory")
#define CP_WAIT(n)  asm volatile("cp.async.wait_group %0;" :: "n"(n) : "memory")

__device__ __forceinline__ float fexp(float x) {
    const float L = 1.4426950408889634f;
    float t = fmaf(x, L, 12582912.0f);
    float n = t - 12582912.0f;
    float r = fmaf(x, L, -n);
    float u = r * 0.6931471805599453f;
    float p = 1.3888889e-3f;
    p = fmaf(p, u, 8.3333333e-3f);
    p = fmaf(p, u, 4.1666667e-2f);
    p = fmaf(p, u, 1.6666667e-1f);
    p = fmaf(p, u, 5.0e-1f);
    p = fmaf(p, u, 1.0f);
    p = fmaf(p, u, 1.0f);
    int e = (int)n;
    return __int_as_float((e + 127) << 23) * p;
}
__device__ __forceinline__ float expm1p(float p) {
    float q = 2.4801587e-5f;
    q = fmaf(q, p, 1.9841270e-4f);
    q = fmaf(q, p, 1.3888889e-3f);
    q = fmaf(q, p, 8.3333333e-3f);
    q = fmaf(q, p, 4.1666667e-2f);
    q = fmaf(q, p, 1.6666667e-1f);
    q = fmaf(q, p, 0.5f);
    q = fmaf(q, p, 1.0f);
    return p * q;
}
__device__ __forceinline__ uint32_t pack_bf16x2(float a, float b) {
    __nv_bfloat162 pk = __floats2bfloat162_rn(a, b);
    return *(uint32_t*)&pk;
}

// ======================= bf16 casts =========================================
__global__ __launch_bounds__(256) void split_x_kernel(const float* __restrict__ x)
{
    int i = (blockIdx.x * 256 + threadIdx.x) * 4;
    float4 v = *(const float4*)(x + i);
    __nv_bfloat16 h[4] = {
        __float2bfloat16(v.x), __float2bfloat16(v.y),
        __float2bfloat16(v.z), __float2bfloat16(v.w) };
    *(uint64_t*)&g_xh[i] = *(const uint64_t*)h;
}

__global__ __launch_bounds__(256) void split_w_kernel(
    const float* __restrict__ Wq, const float* __restrict__ Wk,
    const float* __restrict__ Wv)
{
    const int z = blockIdx.y;
    const float* W = (z == 0) ? Wq : (z == 1) ? Wk : Wv;
    int i = (blockIdx.x * 256 + threadIdx.x) * 4;
    float4 v = *(const float4*)(W + i);
    __nv_bfloat16 h[4] = {
        __float2bfloat16(v.x), __float2bfloat16(v.y),
        __float2bfloat16(v.z), __float2bfloat16(v.w) };
    *(uint64_t*)&g_wh[(size_t)z * DIM * DIM + i] = *(const uint64_t*)h;
}

// ======================= exact colsum via rank-1 identity ===================
__global__ __launch_bounds__(256) void sumx_kernel(const float* __restrict__ x)
{
    const int d = blockIdx.x * 256 + threadIdx.x;
    const int b = blockIdx.y;
    const float* xp = x + (size_t)b * SEQ * DIM + d;
    float s0 = 0, s1 = 0, s2 = 0, s3 = 0;
    for (int s = 0; s < SEQ; s += 4) {
        s0 += xp[(size_t)(s + 0) * DIM];
        s1 += xp[(size_t)(s + 1) * DIM];
        s2 += xp[(size_t)(s + 2) * DIM];
        s3 += xp[(size_t)(s + 3) * DIM];
    }
    g_sx[b * DIM + d] = (s0 + s1) + (s2 + s3);
}

__global__ __launch_bounds__(256) void colsumv_kernel(
    const float* __restrict__ Wv, const float* __restrict__ bv)
{
    const int wid  = threadIdx.x >> 5;
    const int lane = threadIdx.x & 31;
    const int gw   = blockIdx.x * 8 + wid;
    const int n    = gw & (DIM - 1);
    const int b    = gw >> 10;
    const float* wr = Wv + (size_t)n * DIM;
    const float* sx = g_sx + b * DIM;
    float acc = 0.0f;
#pragma unroll
    for (int it = 0; it < 8; it++) {
        int j = (it * 32 + lane) * 4;
        float4 w4 = *(const float4*)(wr + j);
        float4 s4 = *(const float4*)(sx + j);
        acc += w4.x * s4.x + w4.y * s4.y + w4.z * s4.z + w4.w * s4.w;
    }
#pragma unroll
    for (int o = 16; o > 0; o >>= 1)
        acc += __shfl_xor_sync(0xffffffffu, acc, o);
    if (lane == 0) {
        int h = n >> 6, w = n & 63;
        g_colsum[(b * NH + h) * HW + w] = acc + 2048.0f * bv[n];
    }
}

// ======================= QKV projection: 128x128 tiles, cp.async ============
#define ASTR 40

__global__ __launch_bounds__(256) void qkv_kernel(
    const float* __restrict__ bq, const float* __restrict__ bk,
    const float* __restrict__ bv)
{
    __shared__ __align__(16) unsigned short sA[2][128*ASTR];
    __shared__ __align__(16) unsigned short sB[2][128*ASTR];
    __shared__ float s_bias[128];

    const int t    = threadIdx.x;
    const int wid  = t >> 5;
    const int lane = t & 31;
    const int z    = blockIdx.z;
    const int n0   = blockIdx.x * 128;
    const int m0   = blockIdx.y * 128;

    const __nv_bfloat16* wofs = g_wh + (size_t)z * DIM * DIM;

    if (t < 128) {
        const float* bias = (z == 0) ? bq : (z == 1) ? bk : bv;
        s_bias[t] = bias[n0 + t];
    }

    const int wm = wid & 3;        // 4 warps in M (32 rows each)
    const int wn = wid >> 2;       // 2 warps in N (64 cols each)
    const int arow = t >> 2, aseg = t & 3;

    float d[2][8][4];
#pragma unroll
    for (int i = 0; i < 2; i++)
#pragma unroll
        for (int nf = 0; nf < 8; nf++)
#pragma unroll
            for (int r = 0; r < 4; r++) d[i][nf][r] = 0.0f;

    // prologue: chunk 0
#pragma unroll
    for (int i = 0; i < 2; i++) {
        int row = arow + i * 64;
        CP16(smem_u32(&sA[0][row * ASTR + aseg * 8]),
             &g_xh[(size_t)(m0 + row) * DIM + aseg * 8]);
        CP16(smem_u32(&sB[0][row * ASTR + aseg * 8]),
             &wofs[(size_t)(n0 + row) * DIM + aseg * 8]);
    }
    CP_COMMIT();

    for (int kc = 0; kc < 32; kc++) {
        if (kc < 31) {
            const int k0n = (kc + 1) * 32;
            const int bn  = (kc + 1) & 1;
#pragma unroll
            for (int i = 0; i < 2; i++) {
                int row = arow + i * 64;
                CP16(smem_u32(&sA[bn][row * ASTR + aseg * 8]),
                     &g_xh[(size_t)(m0 + row) * DIM + k0n + aseg * 8]);
                CP16(smem_u32(&sB[bn][row * ASTR + aseg * 8]),
                     &wofs[(size_t)(n0 + row) * DIM + k0n + aseg * 8]);
            }
            CP_COMMIT();
            CP_WAIT(1);
        } else {
            CP_WAIT(0);
        }
        __syncthreads();

        const uint32_t au = smem_u32(sA[kc & 1]);
        const uint32_t bu = smem_u32(sB[kc & 1]);
#pragma unroll
        for (int ks = 0; ks < 2; ks++) {
            uint32_t ah0[4], ah1[4];
            ldsm_x4(ah0, au + ((wm * 32 + (lane & 15)) * ASTR
                               + ks * 16 + (lane >> 4) * 8) * 2);
            ldsm_x4(ah1, au + ((wm * 32 + 16 + (lane & 15)) * ASTR
                               + ks * 16 + (lane >> 4) * 8) * 2);
#pragma unroll
            for (int nf = 0; nf < 8; nf++) {
                uint32_t b[2];
                ldsm_x2(b, bu + ((wn * 64 + nf * 8 + (lane & 7)) * ASTR
                                 + ks * 16 + (lane & 8)) * 2);
                mma_bf16(d[0][nf], ah0, b);
                mma_bf16(d[1][nf], ah1, b);
            }
        }
        __syncthreads();
    }

    const int h = (n0 >> 6) + wn;
    __nv_bfloat16* outp = (z == 0) ? g_qb : (z == 1) ? g_kb : g_vb;
#pragma unroll
    for (int i = 0; i < 2; i++) {
        int r = m0 + wm * 32 + i * 16 + (lane >> 2);
#pragma unroll
        for (int nf = 0; nf < 8; nf++) {
            int cl = nf * 8 + 2 * (lane & 3);
            float b0 = s_bias[wn * 64 + cl];
            float b1 = s_bias[wn * 64 + cl + 1];
            float v0 = d[i][nf][0] + b0;
            float v1 = d[i][nf][1] + b1;
            float v2 = d[i][nf][2] + b0;
            float v3 = d[i][nf][3] + b1;
#pragma unroll
            for (int half = 0; half < 2; half++) {
                int rr = r + half * 8;
                int b = rr >> 11, s = rr & (SEQ - 1);
                size_t o = ((size_t)((b * NH + h) * SEQ + s)) * HW + cl;
                *(__nv_bfloat162*)&outp[o] =
                    __floats2bfloat162_rn(half ? v2 : v0, half ? v3 : v1);
            }
        }
    }
}

// ======================= fused attention (512 thr, fused expm1) =============
#define EPAD    2056
#define KVSTR   72
#define KVBYTES (128*KVSTR*2)
#define OFF_E    0
#define OFF_KV   131584
#define OFF_Q    168448
#define OFF_OUT  173056
#define OFF_Z    181248
#define OFF_Z2   181376
#define OFF_CS   181504
#define ATTN_SMEM 181760

__global__ __launch_bounds__(512) void attn_kernel(float* __restrict__ out)
{
    extern __shared__ char dsm[];
    char*  e_p   = dsm + OFF_E;
    char*  kv_p  = dsm + OFF_KV;
    char*  q_p   = dsm + OFF_Q;
    float* s_out = (float*)(dsm + OFF_OUT);
    float* s_z   = (float*)(dsm + OFF_Z);
    float* s_z2  = (float*)(dsm + OFF_Z2);
    float* s_cs  = (float*)(dsm + OFF_CS);

    const uint32_t e_u  = smem_u32(e_p);
    const uint32_t kv_u = smem_u32(kv_p);
    const uint32_t q_u  = smem_u32(q_p);

    const int t    = threadIdx.x;
    const int wid  = t >> 5;
    const int lane = t & 31;
    const int q0   = blockIdx.x * 32;
    const int bh   = blockIdx.y;

    const __nv_bfloat16* qg = g_qb + ((size_t)bh * SEQ + q0) * HW;
    const __nv_bfloat16* kg = g_kb + (size_t)bh * SEQ * HW;
    const __nv_bfloat16* vg = g_vb + (size_t)bh * SEQ * HW;

    const int wm   = wid & 1;
    const int wm16 = wm * 16;
    const int erow = wm16 + (lane >> 2);

    if (t < 32) { s_z[t] = 0.0f; s_z2[t] = 0.0f; }
    if (t < 64) s_cs[t] = g_colsum[bh * HW + t];
    if (t < 256) {
        int row = t >> 3, seg = t & 7;
        *(uint4*)(q_p + (row * KVSTR + seg * 8) * 2) =
            *(const uint4*)(qg + row * HW + seg * 8);
    }
    // prologue: K chunk 0
    {
#pragma unroll
        for (int i = 0; i < 2; i++) {
            int idx = t + i * 512;
            int row = idx >> 3, seg = idx & 7;
            CP16(kv_u + (row * KVSTR + seg * 8) * 2,
                 kg + row * HW + seg * 8);
        }
        CP_COMMIT();
    }
    __syncthreads();

    uint32_t aq[4][4];
#pragma unroll
    for (int ks = 0; ks < 4; ks++) {
        uint32_t off = ((wm16 + (lane & 15)) * KVSTR + ks * 16 + (lane >> 4) * 8) * 2;
        ldsm_x4(aq[ks], q_u + off);
    }

    float zp0 = 0.0f, zp1 = 0.0f;
    const int wq = wid >> 1;

    // ---- phase 1: e = exp(QK^T/8), z ----
    for (int c = 0; c < 16; c++) {
        if (c < 15) {
            const __nv_bfloat16* src = kg + (size_t)(c + 1) * 128 * HW;
            uint32_t dst = kv_u + ((c + 1) & 1) * KVBYTES;
#pragma unroll
            for (int i = 0; i < 2; i++) {
                int idx = t + i * 512;
                int row = idx >> 3, seg = idx & 7;
                CP16(dst + (row * KVSTR + seg * 8) * 2, src + row * HW + seg * 8);
            }
            CP_COMMIT();
            CP_WAIT(1);
        } else {
            CP_WAIT(0);
        }
        __syncthreads();
        const uint32_t buf = kv_u + (c & 1) * KVBYTES;

#pragma unroll
        for (int nf = 0; nf < 2; nf++) {
            float d[4] = {0, 0, 0, 0};
#pragma unroll
            for (int ks = 0; ks < 4; ks++) {
                uint32_t b[2];
                uint32_t off = ((wq * 16 + nf * 8 + (lane & 7)) * KVSTR
                                + ks * 16 + (lane & 8)) * 2;
                ldsm_x2(b, buf + off);
                mma_bf16(d, aq[ks], b);
            }
            float e0 = fexp(d[0] * 0.125f);
            float e1 = fexp(d[1] * 0.125f);
            float e2 = fexp(d[2] * 0.125f);
            float e3 = fexp(d[3] * 0.125f);
            zp0 += e0 + e1;
            zp1 += e2 + e3;
            int col = c * 128 + wq * 16 + nf * 8 + 2 * (lane & 3);
            *(__nv_bfloat162*)(e_p + (erow * EPAD + col) * 2) =
                __floats2bfloat162_rn(e0, e1);
            *(__nv_bfloat162*)(e_p + ((erow + 8) * EPAD + col) * 2) =
                __floats2bfloat162_rn(e2, e3);
        }
        __syncthreads();
    }

    zp0 += __shfl_xor_sync(0xffffffffu, zp0, 1);
    zp0 += __shfl_xor_sync(0xffffffffu, zp0, 2);
    zp1 += __shfl_xor_sync(0xffffffffu, zp1, 1);
    zp1 += __shfl_xor_sync(0xffffffffu, zp1, 2);
    if ((lane & 3) == 0) {
        atomicAdd(&s_z[erow], zp0);
        atomicAdd(&s_z[erow + 8], zp1);
    }
    // zero output tile while z lands
    *(float4*)&s_out[t * 4] = make_float4(0.f, 0.f, 0.f, 0.f);
    __syncthreads();

    const float inv0 = 1.0f / s_z[erow];
    const float inv1 = 1.0f / s_z[erow + 8];

    // ---- phase 3: D = expm1(e/z) @ V, u computed in-register -------------
    {
#pragma unroll
        for (int i = 0; i < 2; i++) {
            int idx = t + i * 512;
            int row = idx >> 3, seg = idx & 7;
            CP16(kv_u + (row * KVSTR + seg * 8) * 2, vg + row * HW + seg * 8);
        }
        CP_COMMIT();
    }

    const int wn = (wid >> 1) & 1;
    const int wk = wid >> 2;

    float dd[4][4];
#pragma unroll
    for (int nf = 0; nf < 4; nf++)
#pragma unroll
        for (int r = 0; r < 4; r++) dd[nf][r] = 0.0f;
    float zu0 = 0.0f, zu1 = 0.0f;

    for (int c = 0; c < 16; c++) {
        if (c < 15) {
            const __nv_bfloat16* src = vg + (size_t)(c + 1) * 128 * HW;
            uint32_t dst = kv_u + ((c + 1) & 1) * KVBYTES;
#pragma unroll
            for (int i = 0; i < 2; i++) {
                int idx = t + i * 512;
                int row = idx >> 3, seg = idx & 7;
                CP16(dst + (row * KVSTR + seg * 8) * 2, src + row * HW + seg * 8);
            }
            CP_COMMIT();
            CP_WAIT(1);
        } else {
            CP_WAIT(0);
        }
        __syncthreads();
        const uint32_t buf = kv_u + (c & 1) * KVBYTES;

#pragma unroll
        for (int ks = 0; ks < 2; ks++) {
            uint32_t au[4];
            uint32_t aoff = ((wm16 + (lane & 15)) * EPAD
                             + c * 128 + wk * 32 + ks * 16 + (lane >> 4) * 8) * 2;
            ldsm_x4(au, e_u + aoff);
            uint32_t ua[4];
#pragma unroll
            for (int j = 0; j < 4; j++) {
                uint32_t bits = au[j];
                float e0 = __uint_as_float(bits << 16);
                float e1 = __uint_as_float(bits & 0xffff0000u);
                float iv = (j & 1) ? inv1 : inv0;
                float u0 = expm1p(e0 * iv);
                float u1 = expm1p(e1 * iv);
                if (j & 1) zu1 += u0 + u1; else zu0 += u0 + u1;
                ua[j] = pack_bf16x2(u0, u1);
            }
#pragma unroll
            for (int nf = 0; nf < 4; nf++) {
                uint32_t b[2];
                uint32_t boff = ((wk * 32 + ks * 16 + (lane & 7) + (lane & 8)) * KVSTR
                                 + wn * 32 + nf * 8) * 2;
                ldsm_x2t(b, buf + boff);
                mma_bf16(dd[nf], ua, b);
            }
        }
        __syncthreads();
    }

    // Sum of u: each element computed by both wn-warps -> halve at use.
    zu0 += __shfl_xor_sync(0xffffffffu, zu0, 1);
    zu0 += __shfl_xor_sync(0xffffffffu, zu0, 2);
    zu1 += __shfl_xor_sync(0xffffffffu, zu1, 1);
    zu1 += __shfl_xor_sync(0xffffffffu, zu1, 2);
    if ((lane & 3) == 0) {
        atomicAdd(&s_z2[erow], zu0);
        atomicAdd(&s_z2[erow + 8], zu1);
    }

    // reduce wk partials into s_out
    {
        int row0 = erow;
#pragma unroll
        for (int nf = 0; nf < 4; nf++) {
            int col = wn * 32 + nf * 8 + 2 * (lane & 3);
            atomicAdd(&s_out[row0 * 64 + col],           dd[nf][0]);
            atomicAdd(&s_out[row0 * 64 + col + 1],       dd[nf][1]);
            atomicAdd(&s_out[(row0 + 8) * 64 + col],     dd[nf][2]);
            atomicAdd(&s_out[(row0 + 8) * 64 + col + 1], dd[nf][3]);
        }
    }
    __syncthreads();

    // ---- epilogue: h = (colsum + D) / (2048 + sum u) ----
    {
        const int b  = bh >> 4, hh = bh & 15;
        const int row = t >> 4;
        const int c0  = (t & 15) * 4;
        float sc = 1.0f / (2048.0f + 0.5f * s_z2[row]);
        float4 a  = *(float4*)&s_out[row * 64 + c0];
        float4 cs = *(float4*)&s_cs[c0];
        float4 o = { (cs.x + a.x) * sc, (cs.y + a.y) * sc,
                     (cs.z + a.z) * sc, (cs.w + a.w) * sc };
        *(float4*)&out[((size_t)(b * SEQ + q0 + row)) * DIM + hh * HW + c0] = o;
    }
}

// ---------------- launch -----------------------------------------------------
extern "C" void kernel_launch(void* const* d_in, const int* in_sizes, int n_in,
                              void* d_out, int out_size)
{
    const float* x  = (const float*)d_in[0];
    const float* Wq = (const float*)d_in[1];
    const float* bq = (const float*)d_in[2];
    const float* Wk = (const float*)d_in[3];
    const float* bk = (const float*)d_in[4];
    const float* Wv = (const float*)d_in[5];
    const float* bv = (const float*)d_in[6];
    float* out = (float*)d_out;

    split_x_kernel<<<MTOT * DIM / 1024, 256>>>(x);
    {
        dim3 gw(DIM * DIM / 1024, 3);
        split_w_kernel<<<gw, 256>>>(Wq, Wk, Wv);
    }
    {
        dim3 gs(DIM / 256, BATCH);
        sumx_kernel<<<gs, 256>>>(x);
    }
    colsumv_kernel<<<BATCH * DIM / 8, 256>>>(Wv, bv);
    {
        dim3 g(DIM / 128, MTOT / 128, 3);
        qkv_kernel<<<g, 256>>>(bq, bk, bv);
    }
    {
        cudaFuncSetAttribute(attn_kernel,
                             cudaFuncAttributeMaxDynamicSharedMemorySize, ATTN_SMEM);
        dim3 g2(SEQ / 32, BHTOT);
        attn_kernel<<<g2, 512, ATTN_SMEM>>>(out);
    }
}

// round 12
// speedup vs baseline: 6.4055x; 1.3655x over previous
#include <cuda_runtime.h>
#include <cuda_bf16.h>
#include <cstdint>

#define BATCH 2
#define SEQ   2048
#define DIM   1024
#define NH    16
#define HW    64
#define BHTOT (BATCH*NH)
#define MTOT  (BATCH*SEQ)

// ---------------- global scratch ----------------
__device__ __nv_bfloat16 g_xh[MTOT*DIM];
__device__ __nv_bfloat16 g_wh[3*DIM*DIM];
__device__ __nv_bfloat16 g_qb[BHTOT*SEQ*HW];
__device__ __nv_bfloat16 g_kb[BHTOT*SEQ*HW];
__device__ __nv_bfloat16 g_vb[BHTOT*SEQ*HW];
__device__ float         g_sx[BATCH*DIM];
__device__ float         g_colsum[BHTOT*HW];

// ---------------- helpers ---------------------------------------------------
__device__ __forceinline__ uint32_t smem_u32(const void* p) {
    uint32_t a;
    asm("{ .reg .u64 t; cvta.to.shared.u64 t, %1; cvt.u32.u64 %0, t; }"
        : "=r"(a) : "l"(p));
    return a;
}
__device__ __forceinline__ void ldsm_x4(uint32_t (&r)[4], uint32_t addr) {
    asm volatile("ldmatrix.sync.aligned.m8n8.x4.shared.b16 {%0,%1,%2,%3}, [%4];"
                 : "=r"(r[0]), "=r"(r[1]), "=r"(r[2]), "=r"(r[3]) : "r"(addr));
}
__device__ __forceinline__ void ldsm_x2(uint32_t (&r)[2], uint32_t addr) {
    asm volatile("ldmatrix.sync.aligned.m8n8.x2.shared.b16 {%0,%1}, [%2];"
                 : "=r"(r[0]), "=r"(r[1]) : "r"(addr));
}
__device__ __forceinline__ void ldsm_x2t(uint32_t (&r)[2], uint32_t addr) {
    asm volatile("ldmatrix.sync.aligned.m8n8.x2.trans.shared.b16 {%0,%1}, [%2];"
                 : "=r"(r[0]), "=r"(r[1]) : "r"(addr));
}
__device__ __forceinline__ void mma_bf16(float (&d)[4], const uint32_t (&a)[4],
                                         const uint32_t (&b)[2]) {
    asm volatile("mma.sync.aligned.m16n8k16.row.col.f32.bf16.bf16.f32 "
                 "{%0,%1,%2,%3}, {%4,%5,%6,%7}, {%8,%9}, {%0,%1,%2,%3};"
                 : "+f"(d[0]), "+f"(d[1]), "+f"(d[2]), "+f"(d[3])
                 : "r"(a[0]), "r"(a[1]), "r"(a[2]), "r"(a[3]),
                   "r"(b[0]), "r"(b[1]));
}
#define CP16(dst, src) \
    asm volatile("cp.async.cg.shared.global [%0], [%1], 16;" \
                 :: "r"(dst), "l"(src))
#define CP_COMMIT() asm volatile("cp.async.commit_group;" ::: "memory")
#define CP_WAIT(n)  asm volatile("cp.async.wait_group %0;" :: "n"(n) : "memory")

__device__ __forceinline__ float fexp(float x) {
    const float L = 1.4426950408889634f;
    float t = fmaf(x, L, 12582912.0f);
    float n = t - 12582912.0f;
    float r = fmaf(x, L, -n);
    float u = r * 0.6931471805599453f;
    float p = 1.3888889e-3f;
    p = fmaf(p, u, 8.3333333e-3f);
    p = fmaf(p, u, 4.1666667e-2f);
    p = fmaf(p, u, 1.6666667e-1f);
    p = fmaf(p, u, 5.0e-1f);
    p = fmaf(p, u, 1.0f);
    p = fmaf(p, u, 1.0f);
    int e = (int)n;
    return __int_as_float((e + 127) << 23) * p;
}
__device__ __forceinline__ uint32_t pack_bf16x2(float a, float b) {
    __nv_bfloat162 pk = __floats2bfloat162_rn(a, b);
    return *(uint32_t*)&pk;
}

// ======================= bf16 casts =========================================
__global__ __launch_bounds__(256) void split_x_kernel(const float* __restrict__ x)
{
    int i = (blockIdx.x * 256 + threadIdx.x) * 4;
    float4 v = *(const float4*)(x + i);
    __nv_bfloat16 h[4] = {
        __float2bfloat16(v.x), __float2bfloat16(v.y),
        __float2bfloat16(v.z), __float2bfloat16(v.w) };
    *(uint64_t*)&g_xh[i] = *(const uint64_t*)h;
}

__global__ __launch_bounds__(256) void split_w_kernel(
    const float* __restrict__ Wq, const float* __restrict__ Wk,
    const float* __restrict__ Wv)
{
    const int z = blockIdx.y;
    const float* W = (z == 0) ? Wq : (z == 1) ? Wk : Wv;
    int i = (blockIdx.x * 256 + threadIdx.x) * 4;
    float4 v = *(const float4*)(W + i);
    __nv_bfloat16 h[4] = {
        __float2bfloat16(v.x), __float2bfloat16(v.y),
        __float2bfloat16(v.z), __float2bfloat16(v.w) };
    *(uint64_t*)&g_wh[(size_t)z * DIM * DIM + i] = *(const uint64_t*)h;
}

// ======================= exact colsum via rank-1 identity ===================
__global__ __launch_bounds__(256) void sumx_kernel(const float* __restrict__ x)
{
    const int d = blockIdx.x * 256 + threadIdx.x;
    const int b = blockIdx.y;
    const float* xp = x + (size_t)b * SEQ * DIM + d;
    float s0 = 0, s1 = 0, s2 = 0, s3 = 0;
    for (int s = 0; s < SEQ; s += 4) {
        s0 += xp[(size_t)(s + 0) * DIM];
        s1 += xp[(size_t)(s + 1) * DIM];
        s2 += xp[(size_t)(s + 2) * DIM];
        s3 += xp[(size_t)(s + 3) * DIM];
    }
    g_sx[b * DIM + d] = (s0 + s1) + (s2 + s3);
}

__global__ __launch_bounds__(256) void colsumv_kernel(
    const float* __restrict__ Wv, const float* __restrict__ bv)
{
    const int wid  = threadIdx.x >> 5;
    const int lane = threadIdx.x & 31;
    const int gw   = blockIdx.x * 8 + wid;
    const int n    = gw & (DIM - 1);
    const int b    = gw >> 10;
    const float* wr = Wv + (size_t)n * DIM;
    const float* sx = g_sx + b * DIM;
    float acc = 0.0f;
#pragma unroll
    for (int it = 0; it < 8; it++) {
        int j = (it * 32 + lane) * 4;
        float4 w4 = *(const float4*)(wr + j);
        float4 s4 = *(const float4*)(sx + j);
        acc += w4.x * s4.x + w4.y * s4.y + w4.z * s4.z + w4.w * s4.w;
    }
#pragma unroll
    for (int o = 16; o > 0; o >>= 1)
        acc += __shfl_xor_sync(0xffffffffu, acc, o);
    if (lane == 0) {
        int h = n >> 6, w = n & 63;
        g_colsum[(b * NH + h) * HW + w] = acc + 2048.0f * bv[n];
    }
}

// ======================= QKV projection: 128x128 tiles, cp.async ============
#define ASTR 40

__global__ __launch_bounds__(256) void qkv_kernel(
    const float* __restrict__ bq, const float* __restrict__ bk,
    const float* __restrict__ bv)
{
    __shared__ __align__(16) unsigned short sA[2][128*ASTR];
    __shared__ __align__(16) unsigned short sB[2][128*ASTR];
    __shared__ float s_bias[128];

    const int t    = threadIdx.x;
    const int wid  = t >> 5;
    const int lane = t & 31;
    const int z    = blockIdx.z;
    const int n0   = blockIdx.x * 128;
    const int m0   = blockIdx.y * 128;

    const __nv_bfloat16* wofs = g_wh + (size_t)z * DIM * DIM;

    if (t < 128) {
        const float* bias = (z == 0) ? bq : (z == 1) ? bk : bv;
        s_bias[t] = bias[n0 + t];
    }

    const int wm = wid & 3;
    const int wn = wid >> 2;
    const int arow = t >> 2, aseg = t & 3;

    float d[2][8][4];
#pragma unroll
    for (int i = 0; i < 2; i++)
#pragma unroll
        for (int nf = 0; nf < 8; nf++)
#pragma unroll
            for (int r = 0; r < 4; r++) d[i][nf][r] = 0.0f;

#pragma unroll
    for (int i = 0; i < 2; i++) {
        int row = arow + i * 64;
        CP16(smem_u32(&sA[0][row * ASTR + aseg * 8]),
             &g_xh[(size_t)(m0 + row) * DIM + aseg * 8]);
        CP16(smem_u32(&sB[0][row * ASTR + aseg * 8]),
             &wofs[(size_t)(n0 + row) * DIM + aseg * 8]);
    }
    CP_COMMIT();

    for (int kc = 0; kc < 32; kc++) {
        if (kc < 31) {
            const int k0n = (kc + 1) * 32;
            const int bn  = (kc + 1) & 1;
#pragma unroll
            for (int i = 0; i < 2; i++) {
                int row = arow + i * 64;
                CP16(smem_u32(&sA[bn][row * ASTR + aseg * 8]),
                     &g_xh[(size_t)(m0 + row) * DIM + k0n + aseg * 8]);
                CP16(smem_u32(&sB[bn][row * ASTR + aseg * 8]),
                     &wofs[(size_t)(n0 + row) * DIM + k0n + aseg * 8]);
            }
            CP_COMMIT();
            CP_WAIT(1);
        } else {
            CP_WAIT(0);
        }
        __syncthreads();

        const uint32_t au = smem_u32(sA[kc & 1]);
        const uint32_t bu = smem_u32(sB[kc & 1]);
#pragma unroll
        for (int ks = 0; ks < 2; ks++) {
            uint32_t ah0[4], ah1[4];
            ldsm_x4(ah0, au + ((wm * 32 + (lane & 15)) * ASTR
                               + ks * 16 + (lane >> 4) * 8) * 2);
            ldsm_x4(ah1, au + ((wm * 32 + 16 + (lane & 15)) * ASTR
                               + ks * 16 + (lane >> 4) * 8) * 2);
#pragma unroll
            for (int nf = 0; nf < 8; nf++) {
                uint32_t b[2];
                ldsm_x2(b, bu + ((wn * 64 + nf * 8 + (lane & 7)) * ASTR
                                 + ks * 16 + (lane & 8)) * 2);
                mma_bf16(d[0][nf], ah0, b);
                mma_bf16(d[1][nf], ah1, b);
            }
        }
        __syncthreads();
    }

    const int h = (n0 >> 6) + wn;
    __nv_bfloat16* outp = (z == 0) ? g_qb : (z == 1) ? g_kb : g_vb;
#pragma unroll
    for (int i = 0; i < 2; i++) {
        int r = m0 + wm * 32 + i * 16 + (lane >> 2);
#pragma unroll
        for (int nf = 0; nf < 8; nf++) {
            int cl = nf * 8 + 2 * (lane & 3);
            float b0 = s_bias[wn * 64 + cl];
            float b1 = s_bias[wn * 64 + cl + 1];
            float v0 = d[i][nf][0] + b0;
            float v1 = d[i][nf][1] + b1;
            float v2 = d[i][nf][2] + b0;
            float v3 = d[i][nf][3] + b1;
#pragma unroll
            for (int half = 0; half < 2; half++) {
                int rr = r + half * 8;
                int b = rr >> 11, s = rr & (SEQ - 1);
                size_t o = ((size_t)((b * NH + h) * SEQ + s)) * HW + cl;
                *(__nv_bfloat162*)&outp[o] =
                    __floats2bfloat162_rn(half ? v2 : v0, half ? v3 : v1);
            }
        }
    }
}

// ============ single-pass fused attention via moment expansion ==============
// h = (colsum + M1/z + M2/(2z^2)) / (2049 + s2/(2z^2))
//   M1 = sum_i e_i v_i, M2 = sum_i e_i^2 v_i, z = sum e, s2 = sum e^2
#define KVSTR   72
#define KVBYTES (128*KVSTR*2)
#define ESTR    136
#define OFF_K    0
#define OFF_V    (2*KVBYTES)                 // 36864
#define OFF_E    (4*KVBYTES)                 // 73728
#define OFF_E2   (OFF_E + 32*ESTR*2)         // 82432
#define OFF_Q    (OFF_E2 + 32*ESTR*2)        // 91136
#define OFF_CS   (OFF_Q + 32*KVSTR*2)        // 95744
#define OFF_Z    (OFF_CS + 256)              // 96000
#define OFF_S2   (OFF_Z + 128)               // 96128
#define ATTN_SMEM (OFF_S2 + 128)             // 96256

__global__ __launch_bounds__(256, 2) void attn_kernel(float* __restrict__ out)
{
    extern __shared__ char dsm[];
    char*  k_p  = dsm + OFF_K;
    char*  v_p  = dsm + OFF_V;
    char*  e_p  = dsm + OFF_E;
    char*  e2_p = dsm + OFF_E2;
    char*  q_p  = dsm + OFF_Q;
    float* s_cs = (float*)(dsm + OFF_CS);
    float* s_z  = (float*)(dsm + OFF_Z);
    float* s_s2 = (float*)(dsm + OFF_S2);

    const uint32_t k_u  = smem_u32(k_p);
    const uint32_t v_u  = smem_u32(v_p);
    const uint32_t e_u  = smem_u32(e_p);
    const uint32_t e2_u = smem_u32(e2_p);
    const uint32_t q_u  = smem_u32(q_p);

    const int t    = threadIdx.x;
    const int wid  = t >> 5;          // 8 warps
    const int lane = t & 31;
    const int q0   = blockIdx.x * 32;
    const int bh   = blockIdx.y;

    const __nv_bfloat16* qg = g_qb + ((size_t)bh * SEQ + q0) * HW;
    const __nv_bfloat16* kg = g_kb + (size_t)bh * SEQ * HW;
    const __nv_bfloat16* vg = g_vb + (size_t)bh * SEQ * HW;

    // QK roles: wm row-half, wq 32-col group
    const int wm   = wid & 1;
    const int wq   = wid >> 1;        // 0..3
    const int wm16 = wm * 16;
    const int erow = wm16 + (lane >> 2);
    // PV roles: same wm row-half; m = moment select; ch = 32-col half of HW
    const int m  = (wid >> 1) & 1;
    const int ch = wid >> 2;

    if (t < 32) { s_z[t] = 0.0f; s_s2[t] = 0.0f; }
    if (t < 64) s_cs[t] = g_colsum[bh * HW + t];
    {   // Q tile 32x64: exactly 256 uint4
        int row = t >> 3, seg = t & 7;
        *(uint4*)(q_p + (row * KVSTR + seg * 8) * 2) =
            *(const uint4*)(qg + row * HW + seg * 8);
    }
    // prologue: K0 + V0
#pragma unroll
    for (int i = 0; i < 4; i++) {
        int idx = t + i * 256;
        int row = idx >> 3, seg = idx & 7;
        CP16(k_u + (row * KVSTR + seg * 8) * 2, kg + row * HW + seg * 8);
        CP16(v_u + (row * KVSTR + seg * 8) * 2, vg + row * HW + seg * 8);
    }
    CP_COMMIT();
    __syncthreads();

    // Q a-frags persist (k=64 -> 4 ks)
    uint32_t aq[4][4];
#pragma unroll
    for (int ks = 0; ks < 4; ks++) {
        uint32_t off = ((wm16 + (lane & 15)) * KVSTR + ks * 16 + (lane >> 4) * 8) * 2;
        ldsm_x4(aq[ks], q_u + off);
    }

    float zp0 = 0.f, zp1 = 0.f, sp0 = 0.f, sp1 = 0.f;   // row sums e / e^2
    float dd[4][4];                                     // PV moment acc
#pragma unroll
    for (int nf = 0; nf < 4; nf++)
#pragma unroll
        for (int r = 0; r < 4; r++) dd[nf][r] = 0.0f;

    for (int c = 0; c < 16; c++) {
        if (c < 15) {
            const __nv_bfloat16* ksrc = kg + (size_t)(c + 1) * 128 * HW;
            const __nv_bfloat16* vsrc = vg + (size_t)(c + 1) * 128 * HW;
            uint32_t kdst = k_u + ((c + 1) & 1) * KVBYTES;
            uint32_t vdst = v_u + ((c + 1) & 1) * KVBYTES;
#pragma unroll
            for (int i = 0; i < 4; i++) {
                int idx = t + i * 256;
                int row = idx >> 3, seg = idx & 7;
                CP16(kdst + (row * KVSTR + seg * 8) * 2, ksrc + row * HW + seg * 8);
                CP16(vdst + (row * KVSTR + seg * 8) * 2, vsrc + row * HW + seg * 8);
            }
            CP_COMMIT();
            CP_WAIT(1);
        } else {
            CP_WAIT(0);
        }
        __syncthreads();   // KV ready; also protects e-chunk reuse from last PV

        // ---- QK stage: e, e^2 for this 32x128 block ----
        const uint32_t kbuf = k_u + (c & 1) * KVBYTES;
#pragma unroll
        for (int nf = 0; nf < 4; nf++) {
            float d[4] = {0, 0, 0, 0};
#pragma unroll
            for (int ks = 0; ks < 4; ks++) {
                uint32_t b[2];
                uint32_t off = ((wq * 32 + nf * 8 + (lane & 7)) * KVSTR
                                + ks * 16 + (lane & 8)) * 2;
                ldsm_x2(b, kbuf + off);
                mma_bf16(d, aq[ks], b);
            }
            float e0 = fexp(d[0] * 0.125f);
            float e1 = fexp(d[1] * 0.125f);
            float e2 = fexp(d[2] * 0.125f);
            float e3 = fexp(d[3] * 0.125f);
            float q0s = e0 * e0, q1s = e1 * e1, q2s = e2 * e2, q3s = e3 * e3;
            zp0 += e0 + e1;  zp1 += e2 + e3;
            sp0 += q0s + q1s; sp1 += q2s + q3s;
            int col = wq * 32 + nf * 8 + 2 * (lane & 3);
            *(uint32_t*)(e_p  + (erow * ESTR + col) * 2)       = pack_bf16x2(e0, e1);
            *(uint32_t*)(e_p  + ((erow + 8) * ESTR + col) * 2) = pack_bf16x2(e2, e3);
            *(uint32_t*)(e2_p + (erow * ESTR + col) * 2)       = pack_bf16x2(q0s, q1s);
            *(uint32_t*)(e2_p + ((erow + 8) * ESTR + col) * 2) = pack_bf16x2(q2s, q3s);
        }
        __syncthreads();   // e-chunk ready

        // ---- PV stage: dd += (m ? e^2 : e) @ V ----
        const uint32_t abuf = m ? e2_u : e_u;
        const uint32_t vbuf = v_u + (c & 1) * KVBYTES;
#pragma unroll
        for (int ks = 0; ks < 8; ks++) {
            uint32_t am[4];
            ldsm_x4(am, abuf + ((wm16 + (lane & 15)) * ESTR
                                + ks * 16 + (lane >> 4) * 8) * 2);
#pragma unroll
            for (int nf = 0; nf < 4; nf++) {
                uint32_t b[2];
                uint32_t boff = ((ks * 16 + (lane & 7) + (lane & 8)) * KVSTR
                                 + ch * 32 + nf * 8) * 2;
                ldsm_x2t(b, vbuf + boff);
                mma_bf16(dd[nf], am, b);
            }
        }
    }

    // row sums: reduce over lanes sharing a row, then across wq warps
    zp0 += __shfl_xor_sync(0xffffffffu, zp0, 1);
    zp0 += __shfl_xor_sync(0xffffffffu, zp0, 2);
    zp1 += __shfl_xor_sync(0xffffffffu, zp1, 1);
    zp1 += __shfl_xor_sync(0xffffffffu, zp1, 2);
    sp0 += __shfl_xor_sync(0xffffffffu, sp0, 1);
    sp0 += __shfl_xor_sync(0xffffffffu, sp0, 2);
    sp1 += __shfl_xor_sync(0xffffffffu, sp1, 1);
    sp1 += __shfl_xor_sync(0xffffffffu, sp1, 2);
    if ((lane & 3) == 0) {
        atomicAdd(&s_z[erow],      zp0);
        atomicAdd(&s_z[erow + 8],  zp1);
        atomicAdd(&s_s2[erow],     sp0);
        atomicAdd(&s_s2[erow + 8], sp1);
    }
    __syncthreads();

    // write M1 / M2 (fp32, 32x64) into e/e2 buffers (disjoint per warp)
    {
        float* Mb = (float*)(m ? e2_p : e_p);
        int r = wm16 + (lane >> 2);
#pragma unroll
        for (int nf = 0; nf < 4; nf++) {
            int col = ch * 32 + nf * 8 + 2 * (lane & 3);
            Mb[r * 64 + col]           = dd[nf][0];
            Mb[r * 64 + col + 1]       = dd[nf][1];
            Mb[(r + 8) * 64 + col]     = dd[nf][2];
            Mb[(r + 8) * 64 + col + 1] = dd[nf][3];
        }
    }
    __syncthreads();

    // epilogue: 256 threads cover 32 rows x 64 cols (8 floats each)
    {
        const float* M1 = (const float*)e_p;
        const float* M2 = (const float*)e2_p;
        const int b  = bh >> 4, hh = bh & 15;
        const int row = t >> 3;
        const int c0  = (t & 7) * 8;
        float z      = s_z[row];
        float invz   = 1.0f / z;
        float i2z2   = 0.5f * invz * invz;
        float den    = 1.0f / (2049.0f + s_s2[row] * i2z2);
        float* op = out + ((size_t)(b * SEQ + q0 + row)) * DIM + hh * HW + c0;
#pragma unroll
        for (int j = 0; j < 8; j += 4) {
            float4 m1 = *(const float4*)&M1[row * 64 + c0 + j];
            float4 m2 = *(const float4*)&M2[row * 64 + c0 + j];
            float4 cs = *(const float4*)&s_cs[c0 + j];
            float4 o;
            o.x = (cs.x + fmaf(m1.x, invz, m2.x * i2z2)) * den;
            o.y = (cs.y + fmaf(m1.y, invz, m2.y * i2z2)) * den;
            o.z = (cs.z + fmaf(m1.z, invz, m2.z * i2z2)) * den;
            o.w = (cs.w + fmaf(m1.w, invz, m2.w * i2z2)) * den;
            *(float4*)(op + j) = o;
        }
    }
}

// ---------------- launch -----------------------------------------------------
extern "C" void kernel_launch(void* const* d_in, const int* in_sizes, int n_in,
                              void* d_out, int out_size)
{
    const float* x  = (const float*)d_in[0];
    const float* Wq = (const float*)d_in[1];
    const float* bq = (const float*)d_in[2];
    const float* Wk = (const float*)d_in[3];
    const float* bk = (const float*)d_in[4];
    const float* Wv = (const float*)d_in[5];
    const float* bv = (const float*)d_in[6];
    float* out = (float*)d_out;

    split_x_kernel<<<MTOT * DIM / 1024, 256>>>(x);
    {
        dim3 gw(DIM * DIM / 1024, 3);
        split_w_kernel<<<gw, 256>>>(Wq, Wk, Wv);
    }
    {
        dim3 gs(DIM / 256, BATCH);
        sumx_kernel<<<gs, 256>>>(x);
    }
    colsumv_kernel<<<BATCH * DIM / 8, 256>>>(Wv, bv);
    {
        dim3 g(DIM / 128, MTOT / 128, 3);
        qkv_kernel<<<g, 256>>>(bq, bk, bv);
    }
    {
        cudaFuncSetAttribute(attn_kernel,
                             cudaFuncAttributeMaxDynamicSharedMemorySize, ATTN_SMEM);
        dim3 g2(SEQ / 32, BHTOT);
        attn_kernel<<<g2, 256, ATTN_SMEM>>>(out);
    }
}